// round 14
// baseline (speedup 1.0000x reference)
#include <cuda_runtime.h>
#include <cuda_bf16.h>
#include <math.h>
#include <stdint.h>

// Problem dims
#define Bsz   32
#define Ssz   1024
#define Dsz   512
#define Hh    16
#define NBlk  12
#define DHd   32
#define FFd   2048
#define MROWS (Bsz*Ssz)            // 32768
#define QKVW  96                   // 3*DHd

typedef __nv_bfloat16 bf16;

// ---------------- scratch (allocation-free: __device__ globals) ----------------
__device__ float g_x  [(size_t)MROWS*Dsz];    // current activations (fp32, resid)
__device__ float g_y  [(size_t)MROWS*Dsz];    // pre-LN temp
__device__ bf16  g_qkvh[(size_t)MROWS*QKVW];  // per-head q|k|v bf16 hi
__device__ bf16  g_qkvl[(size_t)MROWS*QKVW];  // per-head q|k|v bf16 lo
__device__ bf16  g_xhh[(size_t)MROWS*Dsz];    // concat head outs bf16 hi
__device__ bf16  g_xhl[(size_t)MROWS*Dsz];    // concat head outs bf16 lo
__device__ bf16  g_xbh[(size_t)MROWS*Dsz];    // post-LN1 bf16 hi
__device__ bf16  g_xbl[(size_t)MROWS*Dsz];    // post-LN1 bf16 lo
__device__ bf16  g_xch[(size_t)MROWS*Dsz];    // post-LN2 / embed bf16 hi
__device__ bf16  g_xcl[(size_t)MROWS*Dsz];    // post-LN2 / embed bf16 lo
__device__ bf16  g_h1h[(size_t)MROWS*FFd];    // ffn hidden bf16 hi
__device__ bf16  g_h1l[(size_t)MROWS*FFd];    // ffn hidden bf16 lo
__device__ bf16  g_woth[(size_t)NBlk*Dsz*Dsz];   // Wo^T  [N=512,K=512]
__device__ bf16  g_wotl[(size_t)NBlk*Dsz*Dsz];
__device__ bf16  g_w1th[(size_t)NBlk*FFd*Dsz];   // W1^T  [N=2048,K=512]
__device__ bf16  g_w1tl[(size_t)NBlk*FFd*Dsz];
__device__ bf16  g_w2th[(size_t)NBlk*Dsz*FFd];   // W2^T  [N=512,K=2048]
__device__ bf16  g_w2tl[(size_t)NBlk*Dsz*FFd];
__device__ bf16  g_w0th[(size_t)NBlk*QKVW*Dsz];  // W0^T  [96,512]
__device__ bf16  g_w0tl[(size_t)NBlk*QKVW*Dsz];
__device__ bf16  g_whth[(size_t)NBlk*(Hh-1)*QKVW*DHd];   // Wh^T [96,32] per (l,h)
__device__ bf16  g_whtl[(size_t)NBlk*(Hh-1)*QKVW*DHd];

// ================= low-level helpers =================
__device__ __forceinline__ uint32_t smem_u32(const void* p) {
    uint32_t a;
    asm("{ .reg .u64 t; cvta.to.shared.u64 t, %1; cvt.u32.u64 %0, t; }" : "=r"(a) : "l"(p));
    return a;
}
static __device__ __forceinline__ uint32_t swz128(uint32_t off) { return off ^ ((off >> 3) & 0x70u); }

__device__ __forceinline__ void cp16(uint32_t smem, const void* gmem) {
    asm volatile("cp.async.cg.shared.global [%0], [%1], 16;" :: "r"(smem), "l"(gmem));
}
__device__ __forceinline__ void cp_commit() { asm volatile("cp.async.commit_group;"); }
__device__ __forceinline__ void cp_wait0() { asm volatile("cp.async.wait_group 0;"); }
__device__ __forceinline__ void cp_wait1() { asm volatile("cp.async.wait_group 1;"); }

__device__ __forceinline__ void ldm_x4(uint32_t addr, uint32_t& r0, uint32_t& r1, uint32_t& r2, uint32_t& r3) {
    asm volatile("ldmatrix.sync.aligned.m8n8.x4.shared.b16 {%0,%1,%2,%3}, [%4];"
                 : "=r"(r0), "=r"(r1), "=r"(r2), "=r"(r3) : "r"(addr));
}
__device__ __forceinline__ void ldm_x4t(uint32_t addr, uint32_t& r0, uint32_t& r1, uint32_t& r2, uint32_t& r3) {
    asm volatile("ldmatrix.sync.aligned.m8n8.x4.trans.shared.b16 {%0,%1,%2,%3}, [%4];"
                 : "=r"(r0), "=r"(r1), "=r"(r2), "=r"(r3) : "r"(addr));
}
__device__ __forceinline__ void mma16816(float* c, uint32_t a0, uint32_t a1, uint32_t a2, uint32_t a3,
                                         uint32_t b0, uint32_t b1) {
    asm volatile("mma.sync.aligned.m16n8k16.row.col.f32.bf16.bf16.f32 "
                 "{%0,%1,%2,%3}, {%4,%5,%6,%7}, {%8,%9}, {%0,%1,%2,%3};"
                 : "+f"(c[0]), "+f"(c[1]), "+f"(c[2]), "+f"(c[3])
                 : "r"(a0), "r"(a1), "r"(a2), "r"(a3), "r"(b0), "r"(b1));
}
// packed hi/lo split: uh = {bf16(b), bf16(a)}, ul = {bf16(b-hi_b), bf16(a-hi_a)}
__device__ __forceinline__ void pack2(float a, float b, unsigned& uh, unsigned& ul) {
    asm("cvt.rn.bf16x2.f32 %0, %1, %2;" : "=r"(uh) : "f"(b), "f"(a));
    float fa = __uint_as_float(uh << 16);
    float fb = __uint_as_float(uh & 0xffff0000u);
    asm("cvt.rn.bf16x2.f32 %0, %1, %2;" : "=r"(ul) : "f"(b - fb), "f"(a - fa));
}

// ================= embedding + positional encoding (fp32 + hi/lo) =================
__global__ void embed_kernel(const int* __restrict__ tok,
                             const float* __restrict__ emb,
                             float* __restrict__ x,
                             bf16* __restrict__ xh, bf16* __restrict__ xl)
{
    int64_t i2 = ((int64_t)blockIdx.x * blockDim.x + threadIdx.x) * 2;
    if (i2 >= (int64_t)Bsz * Ssz * Dsz) return;
    float vv[2];
    #pragma unroll
    for (int u = 0; u < 2; ++u) {
        int64_t i = i2 + u;
        int d      = (int)(i & (Dsz - 1));
        int64_t bs = i >> 9;
        int s      = (int)(bs & (Ssz - 1));
        int t      = tok[bs];
        int j      = d >> 1;
        float e    = (2.0f * (float)j) / (float)Dsz;
        float freq = expf(-e * 9.210340371976184f);
        float ang  = (float)s * freq;
        float p    = (d & 1) ? cosf(ang) : sinf(ang);
        vv[u] = emb[(int64_t)t * Dsz + d] + p;
        x[i] = vv[u];
    }
    unsigned uh, ul;
    pack2(vv[0], vv[1], uh, ul);
    *(unsigned*)(xh + i2) = uh;
    *(unsigned*)(xl + i2) = ul;
}

// ================= fused weight transpose + bf16 split (single launch) =================
#define WSP_WO_END  3072
#define WSP_W1_END  (WSP_WO_END + 12288)
#define WSP_W2_END  (WSP_W1_END + 12288)
#define WSP_W0_END  (WSP_W2_END + 576)
#define WSP_TOTAL   (WSP_W0_END + 540)

__global__ __launch_bounds__(256)
void wsplit_all(const float* __restrict__ Wo, const float* __restrict__ W1,
                const float* __restrict__ W2, const float* __restrict__ W0,
                const float* __restrict__ Wh,
                bf16* __restrict__ woth, bf16* __restrict__ wotl,
                bf16* __restrict__ w1th, bf16* __restrict__ w1tl,
                bf16* __restrict__ w2th, bf16* __restrict__ w2tl,
                bf16* __restrict__ w0th, bf16* __restrict__ w0tl,
                bf16* __restrict__ whth, bf16* __restrict__ whtl)
{
    __shared__ float t[32][33];
    int b = blockIdx.x;
    const float* W; bf16 *Th, *Tl;
    int K, N, z, nb, kb;
    if (b < WSP_WO_END) {
        z = b >> 8; int r = b & 255; nb = r & 15; kb = r >> 4;
        W = Wo; Th = woth; Tl = wotl; K = Dsz; N = Dsz;
    } else if (b < WSP_W1_END) {
        int i = b - WSP_WO_END; z = i >> 10; int r = i & 1023; nb = r & 63; kb = r >> 6;
        W = W1; Th = w1th; Tl = w1tl; K = Dsz; N = FFd;
    } else if (b < WSP_W2_END) {
        int i = b - WSP_W1_END; z = i >> 10; int r = i & 1023; nb = r & 15; kb = r >> 4;
        W = W2; Th = w2th; Tl = w2tl; K = FFd; N = Dsz;
    } else if (b < WSP_W0_END) {
        int i = b - WSP_W2_END; z = i / 48; int r = i % 48; nb = r % 3; kb = r / 3;
        W = W0; Th = w0th; Tl = w0tl; K = Dsz; N = QKVW;
    } else {
        int i = b - WSP_W0_END; z = i / 3; nb = i % 3; kb = 0;
        W = Wh; Th = whth; Tl = whtl; K = DHd; N = QKVW;
    }
    const float* Wz = W + (size_t)z * K * N;
    bf16* Thz = Th + (size_t)z * K * N;
    bf16* Tlz = Tl + (size_t)z * K * N;
    int n0 = nb * 32, k0 = kb * 32;
    int tx = threadIdx.x & 31, ty = threadIdx.x >> 5;
    #pragma unroll
    for (int i = 0; i < 4; ++i)
        t[ty + i*8][tx] = Wz[(size_t)(k0 + ty + i*8) * N + n0 + tx];
    __syncthreads();
    #pragma unroll
    for (int i = 0; i < 4; ++i) {
        float v = t[tx][ty + i*8];
        bf16 h = __float2bfloat16(v);
        bf16 lo = __float2bfloat16(v - __bfloat162float(h));
        size_t o = (size_t)(n0 + ty + i*8) * K + k0 + tx;
        Thz[o] = h; Tlz[o] = lo;
    }
}

// ================= mma.sync bf16-split GEMM (big GEMMs), 128x64 tile, 2 CTAs/SM =================
#define GBM 128
#define GBN 64
#define GBK 64
#define ST_AH 0
#define ST_AL 16384
#define ST_BH 32768
#define ST_BL 40960
#define STAGE_BYTES 49152
#define GDYN (2*STAGE_BYTES)

template<int EPI>
__global__ __launch_bounds__(256, 2)
void gemm_mma(const bf16* __restrict__ Ah, const bf16* __restrict__ Al,
              const bf16* __restrict__ Bh, const bf16* __restrict__ Bl,
              const float* __restrict__ bias,
              const float* __restrict__ resid,
              float* __restrict__ Cf,
              bf16* __restrict__ Chh, bf16* __restrict__ Chl,
              int K, int Nld)
{
    extern __shared__ char dsm[];
    const uint32_t sb = smem_u32(dsm);

    const int tid  = threadIdx.x;
    const int lane = tid & 31;
    const int w    = tid >> 5;
    const int wm   = w >> 1;
    const int wn   = w & 1;
    const int row0 = blockIdx.y * GBM;
    const int col0 = blockIdx.x * GBN;

    float acc[2][4][4];
    #pragma unroll
    for (int i = 0; i < 2; ++i)
        #pragma unroll
        for (int j = 0; j < 4; ++j)
            #pragma unroll
            for (int k = 0; k < 4; ++k) acc[i][j][k] = 0.f;

    const int nchunks = K / GBK;

    auto load_stage = [&](int c, int st) {
        const uint32_t s0 = sb + st * STAGE_BYTES;
        const size_t kofs = (size_t)c * GBK;
        const int lr = tid >> 3, lc = tid & 7;
        #pragma unroll
        for (int i = 0; i < 4; ++i) {
            int r = lr + i * 32;
            uint32_t so = swz128((uint32_t)(r * 128 + lc * 16));
            size_t g = (size_t)(row0 + r) * K + kofs + lc * 8;
            cp16(s0 + ST_AH + so, Ah + g);
            cp16(s0 + ST_AL + so, Al + g);
        }
        #pragma unroll
        for (int i = 0; i < 2; ++i) {
            int r = lr + i * 32;
            uint32_t so = swz128((uint32_t)(r * 128 + lc * 16));
            size_t g = (size_t)(col0 + r) * K + kofs + lc * 8;
            cp16(s0 + ST_BH + so, Bh + g);
            cp16(s0 + ST_BL + so, Bl + g);
        }
        cp_commit();
    };

    load_stage(0, 0);

    for (int c = 0; c < nchunks; ++c) {
        const int st = c & 1;
        if (c + 1 < nchunks) { load_stage(c + 1, st ^ 1); cp_wait1(); }
        else                 { cp_wait0(); }
        __syncthreads();

        const uint32_t s0 = sb + st * STAGE_BYTES;
        const int arow  = wm * 32 + (lane & 15);
        const int acolb = (lane >> 4) << 4;
        const int bcolb = ((lane >> 3) & 1) << 4;

        #pragma unroll
        for (int slab = 0; slab < 4; ++slab) {
            const int kb = slab * 32;
            uint32_t ah[2][4], al[2][4], bh[2][4], bl[2][4];
            #pragma unroll
            for (int mf = 0; mf < 2; ++mf) {
                uint32_t ao = swz128((uint32_t)((arow + mf*16) * 128 + kb + acolb));
                ldm_x4(s0 + ST_AH + ao, ah[mf][0], ah[mf][1], ah[mf][2], ah[mf][3]);
                ldm_x4(s0 + ST_AL + ao, al[mf][0], al[mf][1], al[mf][2], al[mf][3]);
            }
            #pragma unroll
            for (int ng = 0; ng < 2; ++ng) {
                int nrow = wn * 32 + ng * 16 + ((lane >> 4) << 3) + (lane & 7);
                uint32_t bo = swz128((uint32_t)(nrow * 128 + kb + bcolb));
                ldm_x4(s0 + ST_BH + bo, bh[ng][0], bh[ng][1], bh[ng][2], bh[ng][3]);
                ldm_x4(s0 + ST_BL + bo, bl[ng][0], bl[ng][1], bl[ng][2], bl[ng][3]);
            }
            #pragma unroll
            for (int mf = 0; mf < 2; ++mf) {
                #pragma unroll
                for (int ng = 0; ng < 2; ++ng) {
                    mma16816(acc[mf][2*ng],   ah[mf][0], ah[mf][1], ah[mf][2], ah[mf][3], bh[ng][0], bh[ng][1]);
                    mma16816(acc[mf][2*ng+1], ah[mf][0], ah[mf][1], ah[mf][2], ah[mf][3], bh[ng][2], bh[ng][3]);
                    mma16816(acc[mf][2*ng],   ah[mf][0], ah[mf][1], ah[mf][2], ah[mf][3], bl[ng][0], bl[ng][1]);
                    mma16816(acc[mf][2*ng+1], ah[mf][0], ah[mf][1], ah[mf][2], ah[mf][3], bl[ng][2], bl[ng][3]);
                    mma16816(acc[mf][2*ng],   al[mf][0], al[mf][1], al[mf][2], al[mf][3], bh[ng][0], bh[ng][1]);
                    mma16816(acc[mf][2*ng+1], al[mf][0], al[mf][1], al[mf][2], al[mf][3], bh[ng][2], bh[ng][3]);
                }
            }
        }
        __syncthreads();
    }

    const int rg = lane >> 2;
    const int cg = (lane & 3) * 2;
    #pragma unroll
    for (int mf = 0; mf < 2; ++mf) {
        const int rbase = row0 + wm*32 + mf*16 + rg;
        #pragma unroll
        for (int nf = 0; nf < 4; ++nf) {
            const int col = col0 + wn*32 + nf*8 + cg;
            const float2 bia = *(const float2*)(bias + col);
            float f0 = acc[mf][nf][0] + bia.x;
            float f1 = acc[mf][nf][1] + bia.y;
            float f2 = acc[mf][nf][2] + bia.x;
            float f3 = acc[mf][nf][3] + bia.y;
            if (EPI == 0) {
                const float2 r0v = *(const float2*)(resid + (size_t)rbase * Nld + col);
                const float2 r1v = *(const float2*)(resid + (size_t)(rbase+8) * Nld + col);
                *(float2*)(Cf + (size_t)rbase * Nld + col)     = make_float2(f0 + r0v.x, f1 + r0v.y);
                *(float2*)(Cf + (size_t)(rbase+8) * Nld + col) = make_float2(f2 + r1v.x, f3 + r1v.y);
            } else {
                f0 = fmaxf(f0, 0.f); f1 = fmaxf(f1, 0.f);
                f2 = fmaxf(f2, 0.f); f3 = fmaxf(f3, 0.f);
                unsigned uh0, ul0, uh1, ul1;
                pack2(f0, f1, uh0, ul0);
                pack2(f2, f3, uh1, ul1);
                *(unsigned*)(Chh + (size_t)rbase * Nld + col)     = uh0;
                *(unsigned*)(Chh + (size_t)(rbase+8) * Nld + col) = uh1;
                *(unsigned*)(Chl + (size_t)rbase * Nld + col)     = ul0;
                *(unsigned*)(Chl + (size_t)(rbase+8) * Nld + col) = ul1;
            }
        }
    }
}

// ================= mma projection (128 rows/CTA, 128 threads) =================
#define PTRS 80
#define P_AH 0
#define P_AL 10240
#define P_BH 20480
#define P_BL 28160
#define P_STG 35840
#define P_DYN (2*P_STG)

__global__ __launch_bounds__(128)
void proj_mma(const bf16* __restrict__ Ah, const bf16* __restrict__ Al, int lda,
              const bf16* __restrict__ Wth, const bf16* __restrict__ Wtl,
              const float* __restrict__ bias,
              bf16* __restrict__ Chh, bf16* __restrict__ Chl, int K)
{
    extern __shared__ char psm[];
    const uint32_t sb = smem_u32(psm);
    const int tid = threadIdx.x, lane = tid & 31, w = tid >> 5;
    const int row0 = blockIdx.x * 128;
    const int nch = K / 32;

    auto load = [&](int c, int st) {
        const uint32_t s0 = sb + st * P_STG;
        const int k0 = c * 32;
        #pragma unroll
        for (int i = 0; i < 4; ++i) {
            int idx = tid + i * 128;
            int r = idx >> 2, cc = idx & 3;
            size_t g = (size_t)(row0 + r) * lda + k0 + cc * 8;
            cp16(s0 + P_AH + r * PTRS + cc * 16, Ah + g);
            cp16(s0 + P_AL + r * PTRS + cc * 16, Al + g);
        }
        #pragma unroll
        for (int i = 0; i < 3; ++i) {
            int idx = tid + i * 128;
            int r = idx >> 2, cc = idx & 3;
            size_t g = (size_t)r * K + k0 + cc * 8;
            cp16(s0 + P_BH + r * PTRS + cc * 16, Wth + g);
            cp16(s0 + P_BL + r * PTRS + cc * 16, Wtl + g);
        }
        cp_commit();
    };

    float acc[2][12][4];
    #pragma unroll
    for (int i = 0; i < 2; ++i)
        #pragma unroll
        for (int j = 0; j < 12; ++j)
            #pragma unroll
            for (int k = 0; k < 4; ++k) acc[i][j][k] = 0.f;

    load(0, 0);
    for (int c = 0; c < nch; ++c) {
        const int st = c & 1;
        if (c + 1 < nch) { load(c + 1, st ^ 1); cp_wait1(); }
        else             { cp_wait0(); }
        __syncthreads();
        const uint32_t s0 = sb + st * P_STG;

        #pragma unroll
        for (int ks = 0; ks < 2; ++ks) {
            uint32_t ahf[2][4], alf[2][4];
            #pragma unroll
            for (int mf = 0; mf < 2; ++mf) {
                uint32_t ad = s0 + (uint32_t)((w*32 + mf*16 + (lane & 15)) * PTRS + ks*32 + ((lane >> 4) << 4));
                ldm_x4(ad + P_AH, ahf[mf][0], ahf[mf][1], ahf[mf][2], ahf[mf][3]);
                ldm_x4(ad + P_AL, alf[mf][0], alf[mf][1], alf[mf][2], alf[mf][3]);
            }
            #pragma unroll
            for (int ng = 0; ng < 6; ++ng) {
                uint32_t bhf[4], blf[4];
                uint32_t bd = s0 + (uint32_t)((ng*16 + ((lane >> 4) << 3) + (lane & 7)) * PTRS
                                              + ks*32 + (((lane >> 3) & 1) << 4));
                ldm_x4(bd + P_BH, bhf[0], bhf[1], bhf[2], bhf[3]);
                ldm_x4(bd + P_BL, blf[0], blf[1], blf[2], blf[3]);
                #pragma unroll
                for (int mf = 0; mf < 2; ++mf) {
                    mma16816(acc[mf][2*ng],   ahf[mf][0], ahf[mf][1], ahf[mf][2], ahf[mf][3], bhf[0], bhf[1]);
                    mma16816(acc[mf][2*ng+1], ahf[mf][0], ahf[mf][1], ahf[mf][2], ahf[mf][3], bhf[2], bhf[3]);
                    mma16816(acc[mf][2*ng],   ahf[mf][0], ahf[mf][1], ahf[mf][2], ahf[mf][3], blf[0], blf[1]);
                    mma16816(acc[mf][2*ng+1], ahf[mf][0], ahf[mf][1], ahf[mf][2], ahf[mf][3], blf[2], blf[3]);
                    mma16816(acc[mf][2*ng],   alf[mf][0], alf[mf][1], alf[mf][2], alf[mf][3], bhf[0], bhf[1]);
                    mma16816(acc[mf][2*ng+1], alf[mf][0], alf[mf][1], alf[mf][2], alf[mf][3], bhf[2], bhf[3]);
                }
            }
        }
        __syncthreads();
    }

    const int rg = lane >> 2, cg = (lane & 3) * 2;
    #pragma unroll
    for (int mf = 0; mf < 2; ++mf) {
        const int r0 = row0 + w*32 + mf*16 + rg;
        #pragma unroll
        for (int nf = 0; nf < 12; ++nf) {
            const int col = nf * 8 + cg;
            const float2 bia = *(const float2*)(bias + col);
            float f0 = acc[mf][nf][0] + bia.x;
            float f1 = acc[mf][nf][1] + bia.y;
            float f2 = acc[mf][nf][2] + bia.x;
            float f3 = acc[mf][nf][3] + bia.y;
            unsigned uh0, ul0, uh1, ul1;
            pack2(f0, f1, uh0, ul0);
            pack2(f2, f3, uh1, ul1);
            *(unsigned*)(Chh + (size_t)r0 * QKVW + col)       = uh0;
            *(unsigned*)(Chh + (size_t)(r0+8) * QKVW + col)   = uh1;
            *(unsigned*)(Chl + (size_t)r0 * QKVW + col)       = ul0;
            *(unsigned*)(Chl + (size_t)(r0+8) * QKVW + col)   = ul1;
        }
    }
}

// ================= mma.sync flash attention: 64 q-rows/CTA, phase-batched, dual O banks =================
#define ATTN_SCALE 0.03125f   // 1/sqrt(1024)
#define ATRS 80
#define AQH 0
#define AQL 5120              // 64 rows x 80B
#define AKV0 10240
#define AKVSTG 20480
#define AOKH 0
#define AOKL 5120
#define AOVH 10240
#define AOVL 15360
#define ATTN_DYN 51200        // 10240 Q + 2x20480 KV

__global__ __launch_bounds__(128, 3)
void attn_mma(const bf16* __restrict__ qkvh, const bf16* __restrict__ qkvl,
              bf16* __restrict__ outh, bf16* __restrict__ outl)
{
    extern __shared__ char asmem[];
    const uint32_t sb = smem_u32(asmem);
    const int tid = threadIdx.x, lane = tid & 31, w = tid >> 5;   // 4 warps
    const int b = blockIdx.y;
    const int q0 = blockIdx.x * 64;
    const size_t base = (size_t)b * Ssz * QKVW;

    // stage Q (hi/lo): 64 rows x 4x16B chunks each
    #pragma unroll
    for (int i = 0; i < 2; ++i) {
        int idx = tid + i * 128;
        int r = idx >> 2, c = idx & 3;
        size_t g = base + (size_t)(q0 + r) * QKVW + c * 8;
        cp16(sb + AQH + r * ATRS + c * 16, qkvh + g);
        cp16(sb + AQL + r * ATRS + c * 16, qkvl + g);
    }
    cp_commit();
    // KV chunk 0 (64 keys)
    {
        const uint32_t s0 = sb + AKV0;
        #pragma unroll
        for (int i = 0; i < 2; ++i) {
            int idx = tid + i * 128;
            int r = idx >> 2, c = idx & 3;
            size_t gk = base + (size_t)r * QKVW + 32 + c * 8;
            cp16(s0 + AOKH + r * ATRS + c * 16, qkvh + gk);
            cp16(s0 + AOKL + r * ATRS + c * 16, qkvl + gk);
            cp16(s0 + AOVH + r * ATRS + c * 16, qkvh + gk + 32);
            cp16(s0 + AOVL + r * ATRS + c * 16, qkvl + gk + 32);
        }
        cp_commit();
    }
    cp_wait1();           // Q complete
    __syncthreads();

    // Q fragments: 16 rows per warp, [kslab][4]
    uint32_t qh[2][4], ql[2][4];
    #pragma unroll
    for (int ks = 0; ks < 2; ++ks) {
        uint32_t ad = sb + (uint32_t)((w * 16 + (lane & 15)) * ATRS + ks * 32 + ((lane >> 4) << 4));
        ldm_x4(ad + AQH, qh[ks][0], qh[ks][1], qh[ks][2], qh[ks][3]);
        ldm_x4(ad + AQL, ql[ks][0], ql[ks][1], ql[ks][2], ql[ks][3]);
    }

    // dual O accumulator banks (even/odd key-group) -> 8 chains of depth 6
    float oA[4][4], oB[4][4];
    float lsum[2];
    lsum[0] = 0.f; lsum[1] = 0.f;
    #pragma unroll
    for (int n8 = 0; n8 < 4; ++n8)
        #pragma unroll
        for (int j = 0; j < 4; ++j) { oA[n8][j] = 0.f; oB[n8][j] = 0.f; }

    const int krow  = ((lane >> 4) << 3) + (lane & 7);
    const int kcolb = (((lane >> 3) & 1) << 4);
    const int vrow  = ((lane >> 3) & 1) * 8 + (lane & 7);
    const int vcolb = ((lane >> 4) << 4);

    for (int c = 0; c < 16; ++c) {
        const int st = c & 1;
        if (c < 15) {
            const uint32_t s1 = sb + AKV0 + (st ^ 1) * AKVSTG;
            #pragma unroll
            for (int i = 0; i < 2; ++i) {
                int idx = tid + i * 128;
                int r = idx >> 2, cc = idx & 3;
                size_t gk = base + (size_t)((c + 1) * 64 + r) * QKVW + 32 + cc * 8;
                cp16(s1 + AOKH + r * ATRS + cc * 16, qkvh + gk);
                cp16(s1 + AOKL + r * ATRS + cc * 16, qkvl + gk);
                cp16(s1 + AOVH + r * ATRS + cc * 16, qkvh + gk + 32);
                cp16(s1 + AOVL + r * ATRS + cc * 16, qkvl + gk + 32);
            }
            cp_commit(); cp_wait1();
        } else cp_wait0();
        __syncthreads();

        const uint32_t kb = sb + AKV0 + st * AKVSTG;

        // ---- Phase A: S = Q K^T for ALL 4 groups (8 independent acc chains) ----
        float s[4][2][4];
        #pragma unroll
        for (int g = 0; g < 4; ++g)
            #pragma unroll
            for (int f = 0; f < 2; ++f)
                #pragma unroll
                for (int j = 0; j < 4; ++j) s[g][f][j] = 0.f;

        #pragma unroll
        for (int g = 0; g < 4; ++g) {
            #pragma unroll
            for (int ks = 0; ks < 2; ++ks) {
                uint32_t kh[4], kl[4];
                uint32_t ad = kb + (uint32_t)((g * 16 + krow) * ATRS + ks * 32 + kcolb);
                ldm_x4(ad + AOKH, kh[0], kh[1], kh[2], kh[3]);
                ldm_x4(ad + AOKL, kl[0], kl[1], kl[2], kl[3]);
                mma16816(s[g][0], qh[ks][0], qh[ks][1], qh[ks][2], qh[ks][3], kh[0], kh[1]);
                mma16816(s[g][1], qh[ks][0], qh[ks][1], qh[ks][2], qh[ks][3], kh[2], kh[3]);
                mma16816(s[g][0], qh[ks][0], qh[ks][1], qh[ks][2], qh[ks][3], kl[0], kl[1]);
                mma16816(s[g][1], qh[ks][0], qh[ks][1], qh[ks][2], qh[ks][3], kl[2], kl[3]);
                mma16816(s[g][0], ql[ks][0], ql[ks][1], ql[ks][2], ql[ks][3], kh[0], kh[1]);
                mma16816(s[g][1], ql[ks][0], ql[ks][1], ql[ks][2], ql[ks][3], kh[2], kh[3]);
            }
        }

        // ---- Phase B: exp + pack for ALL groups (batched MUFU/ALU) ----
        uint32_t ph[4][4], pl[4][4];
        #pragma unroll
        for (int g = 0; g < 4; ++g) {
            float p[2][4];
            #pragma unroll
            for (int f = 0; f < 2; ++f)
                #pragma unroll
                for (int j = 0; j < 4; ++j)
                    p[f][j] = __expf(s[g][f][j] * ATTN_SCALE);
            lsum[0] += p[0][0] + p[0][1] + p[1][0] + p[1][1];
            lsum[1] += p[0][2] + p[0][3] + p[1][2] + p[1][3];
            #pragma unroll
            for (int f = 0; f < 2; ++f) {
                pack2(p[f][0], p[f][1], ph[g][2*f],   pl[g][2*f]);
                pack2(p[f][2], p[f][3], ph[g][2*f+1], pl[g][2*f+1]);
            }
        }

        // ---- Phase C: O += P V, even groups -> oA, odd groups -> oB ----
        #pragma unroll
        for (int g = 0; g < 4; ++g) {
            float (*oc)[4] = (g & 1) ? oB : oA;
            uint32_t vh[2][4], vl[2][4];
            #pragma unroll
            for (int nw = 0; nw < 2; ++nw) {
                uint32_t ad = kb + (uint32_t)((g * 16 + vrow) * ATRS + nw * 32 + vcolb);
                ldm_x4t(ad + AOVH, vh[nw][0], vh[nw][1], vh[nw][2], vh[nw][3]);
                ldm_x4t(ad + AOVL, vl[nw][0], vl[nw][1], vl[nw][2], vl[nw][3]);
            }
            #pragma unroll
            for (int n8 = 0; n8 < 4; ++n8) {
                const int nw = n8 >> 1, pr = (n8 & 1) * 2;
                mma16816(oc[n8], ph[g][0], ph[g][1], ph[g][2], ph[g][3], vh[nw][pr], vh[nw][pr+1]);
                mma16816(oc[n8], ph[g][0], ph[g][1], ph[g][2], ph[g][3], vl[nw][pr], vl[nw][pr+1]);
                mma16816(oc[n8], pl[g][0], pl[g][1], pl[g][2], pl[g][3], vh[nw][pr], vh[nw][pr+1]);
            }
        }
        __syncthreads();
    }

    // merge banks, reduce row sums, normalize, store
    #pragma unroll
    for (int hh = 0; hh < 2; ++hh) {
        float v = lsum[hh];
        v += __shfl_xor_sync(0xffffffffu, v, 1);
        v += __shfl_xor_sync(0xffffffffu, v, 2);
        lsum[hh] = 1.f / v;
    }
    const int rg = lane >> 2, cg = (lane & 3) * 2;
    const int r0 = q0 + w * 16 + rg;
    #pragma unroll
    for (int n8 = 0; n8 < 4; ++n8) {
        const int col = n8 * 8 + cg;
        float f0 = (oA[n8][0] + oB[n8][0]) * lsum[0];
        float f1 = (oA[n8][1] + oB[n8][1]) * lsum[0];
        float f2 = (oA[n8][2] + oB[n8][2]) * lsum[1];
        float f3 = (oA[n8][3] + oB[n8][3]) * lsum[1];
        size_t off0 = ((size_t)b * Ssz + r0) * Dsz + col;
        size_t off1 = off0 + (size_t)8 * Dsz;
        unsigned uh0, ul0, uh1, ul1;
        pack2(f0, f1, uh0, ul0);
        pack2(f2, f3, uh1, ul1);
        *(unsigned*)(outh + off0) = uh0;
        *(unsigned*)(outh + off1) = uh1;
        *(unsigned*)(outl + off0) = ul0;
        *(unsigned*)(outl + off1) = ul1;
    }
}

// ================= LayerNorm (512, eps=1e-3), warp-per-row, 4 rows/CTA =================
__global__ __launch_bounds__(128)
void ln_kernel(const float* __restrict__ y, const float* __restrict__ g,
               const float* __restrict__ be, float* __restrict__ x,
               bf16* __restrict__ xh, bf16* __restrict__ xl)
{
    const int warp = threadIdx.x >> 5, lane = threadIdx.x & 31;
    const int row = blockIdx.x * 4 + warp;
    const float* yr = y + (size_t)row * Dsz;

    float4 v[4];
    float sum = 0.f, sq = 0.f;
    #pragma unroll
    for (int i = 0; i < 4; ++i) {
        v[i] = *(const float4*)(yr + (lane + i * 32) * 4);
        sum += v[i].x + v[i].y + v[i].z + v[i].w;
        sq  += v[i].x*v[i].x + v[i].y*v[i].y + v[i].z*v[i].z + v[i].w*v[i].w;
    }
    #pragma unroll
    for (int o = 16; o > 0; o >>= 1) {
        sum += __shfl_xor_sync(0xffffffffu, sum, o);
        sq  += __shfl_xor_sync(0xffffffffu, sq,  o);
    }
    const float mean = sum * (1.f / (float)Dsz);
    const float var  = sq * (1.f / (float)Dsz) - mean * mean;
    const float r    = rsqrtf(var + 1e-3f);

    #pragma unroll
    for (int i = 0; i < 4; ++i) {
        const int d4 = (lane + i * 32) * 4;
        float4 gg = *(const float4*)(g + d4);
        float4 bb = *(const float4*)(be + d4);
        float4 out;
        out.x = (v[i].x - mean) * r * gg.x + bb.x;
        out.y = (v[i].y - mean) * r * gg.y + bb.y;
        out.z = (v[i].z - mean) * r * gg.z + bb.z;
        out.w = (v[i].w - mean) * r * gg.w + bb.w;
        *(float4*)(x + (size_t)row * Dsz + d4) = out;
        uint2 uh, ul;
        pack2(out.x, out.y, uh.x, ul.x);
        pack2(out.z, out.w, uh.y, ul.y);
        *(uint2*)(xh + (size_t)row * Dsz + d4) = uh;
        *(uint2*)(xl + (size_t)row * Dsz + d4) = ul;
    }
}

// ================= mean-pool + final dense + sigmoid =================
__global__ __launch_bounds__(256)
void final_kernel(const float* __restrict__ x, const float* __restrict__ Wf,
                  const float* __restrict__ bf_, float* __restrict__ out, int out_size)
{
    const int b = blockIdx.x;
    const float* xb = x + (size_t)b * Ssz * Dsz;
    float acc = 0.f;
    for (int i = threadIdx.x; i < (Ssz * Dsz) / 4; i += 256) {
        float4 v = *(const float4*)(xb + (size_t)i * 4);
        int d = (i * 4) & (Dsz - 1);
        acc += v.x * Wf[d] + v.y * Wf[d+1] + v.z * Wf[d+2] + v.w * Wf[d+3];
    }
    #pragma unroll
    for (int o = 16; o > 0; o >>= 1) acc += __shfl_down_sync(0xffffffffu, acc, o);
    __shared__ float ws[8];
    int warp = threadIdx.x >> 5, lane = threadIdx.x & 31;
    if (lane == 0) ws[warp] = acc;
    __syncthreads();
    if (threadIdx.x == 0) {
        float tot = 0.f;
        #pragma unroll
        for (int w = 0; w < 8; ++w) tot += ws[w];
        float logit = tot * (1.f / (float)Ssz) + bf_[0];
        if (b < out_size) out[b] = logit;
        if (Bsz + b < out_size) out[Bsz + b] = 1.f / (1.f + expf(-logit));
    }
}

// ================= orchestration =================
extern "C" void kernel_launch(void* const* d_in, const int* in_sizes, int n_in,
                              void* d_out, int out_size)
{
    const int*   tok = (const int*)  d_in[0];
    const float* emb = (const float*)d_in[1];
    const float* W0  = (const float*)d_in[2];
    const float* b0  = (const float*)d_in[3];
    const float* Wh  = (const float*)d_in[4];
    const float* bh  = (const float*)d_in[5];
    const float* Wo  = (const float*)d_in[6];
    const float* bo  = (const float*)d_in[7];
    const float* g1  = (const float*)d_in[8];
    const float* be1 = (const float*)d_in[9];
    const float* W1  = (const float*)d_in[10];
    const float* b1  = (const float*)d_in[11];
    const float* W2  = (const float*)d_in[12];
    const float* b2  = (const float*)d_in[13];
    const float* g2  = (const float*)d_in[14];
    const float* be2 = (const float*)d_in[15];
    const float* Wf  = (const float*)d_in[16];
    const float* bf_ = (const float*)d_in[17];
    float* out = (float*)d_out;

    float *x, *y;
    bf16 *qkvh, *qkvl, *xhh, *xhl, *xbh, *xbl, *xch, *xcl, *h1h, *h1l;
    bf16 *woth, *wotl, *w1th, *w1tl, *w2th, *w2tl, *w0th, *w0tl, *whth, *whtl;
    cudaGetSymbolAddress((void**)&x,    g_x);
    cudaGetSymbolAddress((void**)&y,    g_y);
    cudaGetSymbolAddress((void**)&qkvh, g_qkvh);
    cudaGetSymbolAddress((void**)&qkvl, g_qkvl);
    cudaGetSymbolAddress((void**)&xhh,  g_xhh);
    cudaGetSymbolAddress((void**)&xhl,  g_xhl);
    cudaGetSymbolAddress((void**)&xbh,  g_xbh);
    cudaGetSymbolAddress((void**)&xbl,  g_xbl);
    cudaGetSymbolAddress((void**)&xch,  g_xch);
    cudaGetSymbolAddress((void**)&xcl,  g_xcl);
    cudaGetSymbolAddress((void**)&h1h,  g_h1h);
    cudaGetSymbolAddress((void**)&h1l,  g_h1l);
    cudaGetSymbolAddress((void**)&woth, g_woth);
    cudaGetSymbolAddress((void**)&wotl, g_wotl);
    cudaGetSymbolAddress((void**)&w1th, g_w1th);
    cudaGetSymbolAddress((void**)&w1tl, g_w1tl);
    cudaGetSymbolAddress((void**)&w2th, g_w2th);
    cudaGetSymbolAddress((void**)&w2tl, g_w2tl);
    cudaGetSymbolAddress((void**)&w0th, g_w0th);
    cudaGetSymbolAddress((void**)&w0tl, g_w0tl);
    cudaGetSymbolAddress((void**)&whth, g_whth);
    cudaGetSymbolAddress((void**)&whtl, g_whtl);

    cudaFuncSetAttribute(gemm_mma<0>, cudaFuncAttributeMaxDynamicSharedMemorySize, GDYN);
    cudaFuncSetAttribute(gemm_mma<1>, cudaFuncAttributeMaxDynamicSharedMemorySize, GDYN);
    cudaFuncSetAttribute(attn_mma,    cudaFuncAttributeMaxDynamicSharedMemorySize, ATTN_DYN);
    cudaFuncSetAttribute(proj_mma,    cudaFuncAttributeMaxDynamicSharedMemorySize, P_DYN);

    {
        int64_t tot = (int64_t)Bsz * Ssz * Dsz / 2;
        embed_kernel<<<(unsigned)((tot + 255) / 256), 256>>>(tok, emb, x, xch, xcl);
    }

    // fused weight transpose + bf16 split (one launch)
    wsplit_all<<<WSP_TOTAL, 256>>>(Wo, W1, W2, W0, Wh,
                                   woth, wotl, w1th, w1tl, w2th, w2tl,
                                   w0th, w0tl, whth, whtl);

    const dim3 attn_grid(Ssz / 64, Bsz);         // (16, 32) = 512 CTAs
    const dim3 tc_wo(Dsz / GBN,  MROWS / GBM);   // (8, 256)
    const dim3 tc_f1(FFd / GBN,  MROWS / GBM);   // (32, 256)
    const dim3 tc_f2(Dsz / GBN,  MROWS / GBM);   // (8, 256)

    for (int l = 0; l < NBlk; ++l) {
        // head 0: D -> 96 (mma, reads post-LN2/embed hi/lo)
        proj_mma<<<MROWS/128, 128, P_DYN>>>(xch, xcl, Dsz,
            w0th + (size_t)l * QKVW * Dsz, w0tl + (size_t)l * QKVW * Dsz,
            b0 + (size_t)l * QKVW, qkvh, qkvl, Dsz);
        attn_mma<<<attn_grid, 128, ATTN_DYN>>>(qkvh, qkvl, xhh, xhl);

        // chained heads 1..15: DH -> 96
        for (int h = 1; h < Hh; ++h) {
            const size_t wo = ((size_t)l * (Hh - 1) + (h - 1)) * QKVW * DHd;
            proj_mma<<<MROWS/128, 128, P_DYN>>>(
                xhh + (size_t)(h - 1) * DHd, xhl + (size_t)(h - 1) * DHd, Dsz,
                whth + wo, whtl + wo,
                bh + ((size_t)l * (Hh - 1) + (h - 1)) * QKVW, qkvh, qkvl, DHd);
            attn_mma<<<attn_grid, 128, ATTN_DYN>>>(qkvh, qkvl,
                xhh + (size_t)h * DHd, xhl + (size_t)h * DHd);
        }

        // output projection + residual (mma), then LN1 (emit bf16)
        gemm_mma<0><<<tc_wo, 256, GDYN>>>(xhh, xhl,
            woth + (size_t)l * Dsz * Dsz, wotl + (size_t)l * Dsz * Dsz,
            bo + (size_t)l * Dsz, x, y, nullptr, nullptr, Dsz, Dsz);
        ln_kernel<<<MROWS/4, 128>>>(y, g1 + (size_t)l * Dsz, be1 + (size_t)l * Dsz,
                                    x, xbh, xbl);

        // FFN1 (mma, relu -> bf16 split)
        gemm_mma<1><<<tc_f1, 256, GDYN>>>(xbh, xbl,
            w1th + (size_t)l * FFd * Dsz, w1tl + (size_t)l * FFd * Dsz,
            b1 + (size_t)l * FFd, nullptr, nullptr, h1h, h1l, Dsz, FFd);

        // FFN2 (mma) + residual, then LN2 (emit bf16 for next layer head0)
        gemm_mma<0><<<tc_f2, 256, GDYN>>>(h1h, h1l,
            w2th + (size_t)l * Dsz * FFd, w2tl + (size_t)l * Dsz * FFd,
            b2 + (size_t)l * Dsz, x, y, nullptr, nullptr, FFd, Dsz);
        ln_kernel<<<MROWS/4, 128>>>(y, g2 + (size_t)l * Dsz, be2 + (size_t)l * Dsz,
                                    x, xch, xcl);
    }

    final_kernel<<<Bsz, 256>>>(x, Wf, bf_, out, out_size);
}

// round 16
// speedup vs baseline: 1.0252x; 1.0252x over previous
#include <cuda_runtime.h>
#include <cuda_bf16.h>
#include <math.h>
#include <stdint.h>

// Problem dims
#define Bsz   32
#define Ssz   1024
#define Dsz   512
#define Hh    16
#define NBlk  12
#define DHd   32
#define FFd   2048
#define MROWS (Bsz*Ssz)            // 32768
#define QKVW  96                   // 3*DHd

typedef __nv_bfloat16 bf16;

// ---------------- scratch (allocation-free: __device__ globals) ----------------
__device__ float g_x  [(size_t)MROWS*Dsz];    // current activations (fp32, resid)
__device__ float g_y  [(size_t)MROWS*Dsz];    // pre-LN temp
__device__ bf16  g_qkvh[(size_t)MROWS*QKVW];  // per-head q|k|v bf16 hi
__device__ bf16  g_qkvl[(size_t)MROWS*QKVW];  // per-head q|k|v bf16 lo
__device__ bf16  g_xhh[(size_t)MROWS*Dsz];    // concat head outs bf16 hi
__device__ bf16  g_xhl[(size_t)MROWS*Dsz];    // concat head outs bf16 lo
__device__ bf16  g_xbh[(size_t)MROWS*Dsz];    // post-LN1 bf16 hi
__device__ bf16  g_xbl[(size_t)MROWS*Dsz];    // post-LN1 bf16 lo
__device__ bf16  g_xch[(size_t)MROWS*Dsz];    // post-LN2 / embed bf16 hi
__device__ bf16  g_xcl[(size_t)MROWS*Dsz];    // post-LN2 / embed bf16 lo
__device__ bf16  g_h1h[(size_t)MROWS*FFd];    // ffn hidden bf16 hi
__device__ bf16  g_h1l[(size_t)MROWS*FFd];    // ffn hidden bf16 lo
__device__ bf16  g_woth[(size_t)NBlk*Dsz*Dsz];   // Wo^T  [N=512,K=512]
__device__ bf16  g_wotl[(size_t)NBlk*Dsz*Dsz];
__device__ bf16  g_w1th[(size_t)NBlk*FFd*Dsz];   // W1^T  [N=2048,K=512]
__device__ bf16  g_w1tl[(size_t)NBlk*FFd*Dsz];
__device__ bf16  g_w2th[(size_t)NBlk*Dsz*FFd];   // W2^T  [N=512,K=2048]
__device__ bf16  g_w2tl[(size_t)NBlk*Dsz*FFd];
__device__ bf16  g_w0th[(size_t)NBlk*QKVW*Dsz];  // W0^T  [96,512]
__device__ bf16  g_w0tl[(size_t)NBlk*QKVW*Dsz];
__device__ bf16  g_whth[(size_t)NBlk*(Hh-1)*QKVW*DHd];   // Wh^T [96,32] per (l,h)
__device__ bf16  g_whtl[(size_t)NBlk*(Hh-1)*QKVW*DHd];

// ================= low-level helpers =================
__device__ __forceinline__ uint32_t smem_u32(const void* p) {
    uint32_t a;
    asm("{ .reg .u64 t; cvta.to.shared.u64 t, %1; cvt.u32.u64 %0, t; }" : "=r"(a) : "l"(p));
    return a;
}
static __device__ __forceinline__ uint32_t swz128(uint32_t off) { return off ^ ((off >> 3) & 0x70u); }

__device__ __forceinline__ void cp16(uint32_t smem, const void* gmem) {
    asm volatile("cp.async.cg.shared.global [%0], [%1], 16;" :: "r"(smem), "l"(gmem));
}
__device__ __forceinline__ void cp_commit() { asm volatile("cp.async.commit_group;"); }
__device__ __forceinline__ void cp_wait0() { asm volatile("cp.async.wait_group 0;"); }
__device__ __forceinline__ void cp_wait1() { asm volatile("cp.async.wait_group 1;"); }

__device__ __forceinline__ void ldm_x4(uint32_t addr, uint32_t& r0, uint32_t& r1, uint32_t& r2, uint32_t& r3) {
    asm volatile("ldmatrix.sync.aligned.m8n8.x4.shared.b16 {%0,%1,%2,%3}, [%4];"
                 : "=r"(r0), "=r"(r1), "=r"(r2), "=r"(r3) : "r"(addr));
}
__device__ __forceinline__ void ldm_x4t(uint32_t addr, uint32_t& r0, uint32_t& r1, uint32_t& r2, uint32_t& r3) {
    asm volatile("ldmatrix.sync.aligned.m8n8.x4.trans.shared.b16 {%0,%1,%2,%3}, [%4];"
                 : "=r"(r0), "=r"(r1), "=r"(r2), "=r"(r3) : "r"(addr));
}
__device__ __forceinline__ void mma16816(float* c, uint32_t a0, uint32_t a1, uint32_t a2, uint32_t a3,
                                         uint32_t b0, uint32_t b1) {
    asm volatile("mma.sync.aligned.m16n8k16.row.col.f32.bf16.bf16.f32 "
                 "{%0,%1,%2,%3}, {%4,%5,%6,%7}, {%8,%9}, {%0,%1,%2,%3};"
                 : "+f"(c[0]), "+f"(c[1]), "+f"(c[2]), "+f"(c[3])
                 : "r"(a0), "r"(a1), "r"(a2), "r"(a3), "r"(b0), "r"(b1));
}
// packed hi/lo split: uh = {bf16(b), bf16(a)}, ul = {bf16(b-hi_b), bf16(a-hi_a)}
__device__ __forceinline__ void pack2(float a, float b, unsigned& uh, unsigned& ul) {
    asm("cvt.rn.bf16x2.f32 %0, %1, %2;" : "=r"(uh) : "f"(b), "f"(a));
    float fa = __uint_as_float(uh << 16);
    float fb = __uint_as_float(uh & 0xffff0000u);
    asm("cvt.rn.bf16x2.f32 %0, %1, %2;" : "=r"(ul) : "f"(b - fb), "f"(a - fa));
}

// ================= embedding + positional encoding (fp32 + hi/lo) =================
__global__ void embed_kernel(const int* __restrict__ tok,
                             const float* __restrict__ emb,
                             float* __restrict__ x,
                             bf16* __restrict__ xh, bf16* __restrict__ xl)
{
    int64_t i2 = ((int64_t)blockIdx.x * blockDim.x + threadIdx.x) * 2;
    if (i2 >= (int64_t)Bsz * Ssz * Dsz) return;
    float vv[2];
    #pragma unroll
    for (int u = 0; u < 2; ++u) {
        int64_t i = i2 + u;
        int d      = (int)(i & (Dsz - 1));
        int64_t bs = i >> 9;
        int s      = (int)(bs & (Ssz - 1));
        int t      = tok[bs];
        int j      = d >> 1;
        float e    = (2.0f * (float)j) / (float)Dsz;
        float freq = expf(-e * 9.210340371976184f);
        float ang  = (float)s * freq;
        float p    = (d & 1) ? cosf(ang) : sinf(ang);
        vv[u] = emb[(int64_t)t * Dsz + d] + p;
        x[i] = vv[u];
    }
    unsigned uh, ul;
    pack2(vv[0], vv[1], uh, ul);
    *(unsigned*)(xh + i2) = uh;
    *(unsigned*)(xl + i2) = ul;
}

// ================= fused weight transpose + bf16 split (single launch) =================
#define WSP_WO_END  3072
#define WSP_W1_END  (WSP_WO_END + 12288)
#define WSP_W2_END  (WSP_W1_END + 12288)
#define WSP_W0_END  (WSP_W2_END + 576)
#define WSP_TOTAL   (WSP_W0_END + 540)

__global__ __launch_bounds__(256)
void wsplit_all(const float* __restrict__ Wo, const float* __restrict__ W1,
                const float* __restrict__ W2, const float* __restrict__ W0,
                const float* __restrict__ Wh,
                bf16* __restrict__ woth, bf16* __restrict__ wotl,
                bf16* __restrict__ w1th, bf16* __restrict__ w1tl,
                bf16* __restrict__ w2th, bf16* __restrict__ w2tl,
                bf16* __restrict__ w0th, bf16* __restrict__ w0tl,
                bf16* __restrict__ whth, bf16* __restrict__ whtl)
{
    __shared__ float t[32][33];
    int b = blockIdx.x;
    const float* W; bf16 *Th, *Tl;
    int K, N, z, nb, kb;
    if (b < WSP_WO_END) {
        z = b >> 8; int r = b & 255; nb = r & 15; kb = r >> 4;
        W = Wo; Th = woth; Tl = wotl; K = Dsz; N = Dsz;
    } else if (b < WSP_W1_END) {
        int i = b - WSP_WO_END; z = i >> 10; int r = i & 1023; nb = r & 63; kb = r >> 6;
        W = W1; Th = w1th; Tl = w1tl; K = Dsz; N = FFd;
    } else if (b < WSP_W2_END) {
        int i = b - WSP_W1_END; z = i >> 10; int r = i & 1023; nb = r & 15; kb = r >> 4;
        W = W2; Th = w2th; Tl = w2tl; K = FFd; N = Dsz;
    } else if (b < WSP_W0_END) {
        int i = b - WSP_W2_END; z = i / 48; int r = i % 48; nb = r % 3; kb = r / 3;
        W = W0; Th = w0th; Tl = w0tl; K = Dsz; N = QKVW;
    } else {
        int i = b - WSP_W0_END; z = i / 3; nb = i % 3; kb = 0;
        W = Wh; Th = whth; Tl = whtl; K = DHd; N = QKVW;
    }
    const float* Wz = W + (size_t)z * K * N;
    bf16* Thz = Th + (size_t)z * K * N;
    bf16* Tlz = Tl + (size_t)z * K * N;
    int n0 = nb * 32, k0 = kb * 32;
    int tx = threadIdx.x & 31, ty = threadIdx.x >> 5;
    #pragma unroll
    for (int i = 0; i < 4; ++i)
        t[ty + i*8][tx] = Wz[(size_t)(k0 + ty + i*8) * N + n0 + tx];
    __syncthreads();
    #pragma unroll
    for (int i = 0; i < 4; ++i) {
        float v = t[tx][ty + i*8];
        bf16 h = __float2bfloat16(v);
        bf16 lo = __float2bfloat16(v - __bfloat162float(h));
        size_t o = (size_t)(n0 + ty + i*8) * K + k0 + tx;
        Thz[o] = h; Tlz[o] = lo;
    }
}

// ================= mma.sync bf16-split GEMM (big GEMMs), 128x64 tile, 2 CTAs/SM =================
#define GBM 128
#define GBN 64
#define GBK 64
#define ST_AH 0
#define ST_AL 16384
#define ST_BH 32768
#define ST_BL 40960
#define STAGE_BYTES 49152
#define GDYN (2*STAGE_BYTES)

template<int EPI>
__global__ __launch_bounds__(256, 2)
void gemm_mma(const bf16* __restrict__ Ah, const bf16* __restrict__ Al,
              const bf16* __restrict__ Bh, const bf16* __restrict__ Bl,
              const float* __restrict__ bias,
              const float* __restrict__ resid,
              float* __restrict__ Cf,
              bf16* __restrict__ Chh, bf16* __restrict__ Chl,
              int K, int Nld)
{
    extern __shared__ char dsm[];
    const uint32_t sb = smem_u32(dsm);

    const int tid  = threadIdx.x;
    const int lane = tid & 31;
    const int w    = tid >> 5;
    const int wm   = w >> 1;
    const int wn   = w & 1;
    const int row0 = blockIdx.y * GBM;
    const int col0 = blockIdx.x * GBN;

    float acc[2][4][4];
    #pragma unroll
    for (int i = 0; i < 2; ++i)
        #pragma unroll
        for (int j = 0; j < 4; ++j)
            #pragma unroll
            for (int k = 0; k < 4; ++k) acc[i][j][k] = 0.f;

    const int nchunks = K / GBK;

    auto load_stage = [&](int c, int st) {
        const uint32_t s0 = sb + st * STAGE_BYTES;
        const size_t kofs = (size_t)c * GBK;
        const int lr = tid >> 3, lc = tid & 7;
        #pragma unroll
        for (int i = 0; i < 4; ++i) {
            int r = lr + i * 32;
            uint32_t so = swz128((uint32_t)(r * 128 + lc * 16));
            size_t g = (size_t)(row0 + r) * K + kofs + lc * 8;
            cp16(s0 + ST_AH + so, Ah + g);
            cp16(s0 + ST_AL + so, Al + g);
        }
        #pragma unroll
        for (int i = 0; i < 2; ++i) {
            int r = lr + i * 32;
            uint32_t so = swz128((uint32_t)(r * 128 + lc * 16));
            size_t g = (size_t)(col0 + r) * K + kofs + lc * 8;
            cp16(s0 + ST_BH + so, Bh + g);
            cp16(s0 + ST_BL + so, Bl + g);
        }
        cp_commit();
    };

    load_stage(0, 0);

    for (int c = 0; c < nchunks; ++c) {
        const int st = c & 1;
        if (c + 1 < nchunks) { load_stage(c + 1, st ^ 1); cp_wait1(); }
        else                 { cp_wait0(); }
        __syncthreads();

        const uint32_t s0 = sb + st * STAGE_BYTES;
        const int arow  = wm * 32 + (lane & 15);
        const int acolb = (lane >> 4) << 4;
        const int bcolb = ((lane >> 3) & 1) << 4;

        #pragma unroll
        for (int slab = 0; slab < 4; ++slab) {
            const int kb = slab * 32;
            uint32_t ah[2][4], al[2][4], bh[2][4], bl[2][4];
            #pragma unroll
            for (int mf = 0; mf < 2; ++mf) {
                uint32_t ao = swz128((uint32_t)((arow + mf*16) * 128 + kb + acolb));
                ldm_x4(s0 + ST_AH + ao, ah[mf][0], ah[mf][1], ah[mf][2], ah[mf][3]);
                ldm_x4(s0 + ST_AL + ao, al[mf][0], al[mf][1], al[mf][2], al[mf][3]);
            }
            #pragma unroll
            for (int ng = 0; ng < 2; ++ng) {
                int nrow = wn * 32 + ng * 16 + ((lane >> 4) << 3) + (lane & 7);
                uint32_t bo = swz128((uint32_t)(nrow * 128 + kb + bcolb));
                ldm_x4(s0 + ST_BH + bo, bh[ng][0], bh[ng][1], bh[ng][2], bh[ng][3]);
                ldm_x4(s0 + ST_BL + bo, bl[ng][0], bl[ng][1], bl[ng][2], bl[ng][3]);
            }
            #pragma unroll
            for (int mf = 0; mf < 2; ++mf) {
                #pragma unroll
                for (int ng = 0; ng < 2; ++ng) {
                    mma16816(acc[mf][2*ng],   ah[mf][0], ah[mf][1], ah[mf][2], ah[mf][3], bh[ng][0], bh[ng][1]);
                    mma16816(acc[mf][2*ng+1], ah[mf][0], ah[mf][1], ah[mf][2], ah[mf][3], bh[ng][2], bh[ng][3]);
                    mma16816(acc[mf][2*ng],   ah[mf][0], ah[mf][1], ah[mf][2], ah[mf][3], bl[ng][0], bl[ng][1]);
                    mma16816(acc[mf][2*ng+1], ah[mf][0], ah[mf][1], ah[mf][2], ah[mf][3], bl[ng][2], bl[ng][3]);
                    mma16816(acc[mf][2*ng],   al[mf][0], al[mf][1], al[mf][2], al[mf][3], bh[ng][0], bh[ng][1]);
                    mma16816(acc[mf][2*ng+1], al[mf][0], al[mf][1], al[mf][2], al[mf][3], bh[ng][2], bh[ng][3]);
                }
            }
        }
        __syncthreads();
    }

    const int rg = lane >> 2;
    const int cg = (lane & 3) * 2;
    #pragma unroll
    for (int mf = 0; mf < 2; ++mf) {
        const int rbase = row0 + wm*32 + mf*16 + rg;
        #pragma unroll
        for (int nf = 0; nf < 4; ++nf) {
            const int col = col0 + wn*32 + nf*8 + cg;
            const float2 bia = *(const float2*)(bias + col);
            float f0 = acc[mf][nf][0] + bia.x;
            float f1 = acc[mf][nf][1] + bia.y;
            float f2 = acc[mf][nf][2] + bia.x;
            float f3 = acc[mf][nf][3] + bia.y;
            if (EPI == 0) {
                const float2 r0v = *(const float2*)(resid + (size_t)rbase * Nld + col);
                const float2 r1v = *(const float2*)(resid + (size_t)(rbase+8) * Nld + col);
                *(float2*)(Cf + (size_t)rbase * Nld + col)     = make_float2(f0 + r0v.x, f1 + r0v.y);
                *(float2*)(Cf + (size_t)(rbase+8) * Nld + col) = make_float2(f2 + r1v.x, f3 + r1v.y);
            } else {
                f0 = fmaxf(f0, 0.f); f1 = fmaxf(f1, 0.f);
                f2 = fmaxf(f2, 0.f); f3 = fmaxf(f3, 0.f);
                unsigned uh0, ul0, uh1, ul1;
                pack2(f0, f1, uh0, ul0);
                pack2(f2, f3, uh1, ul1);
                *(unsigned*)(Chh + (size_t)rbase * Nld + col)     = uh0;
                *(unsigned*)(Chh + (size_t)(rbase+8) * Nld + col) = uh1;
                *(unsigned*)(Chl + (size_t)rbase * Nld + col)     = ul0;
                *(unsigned*)(Chl + (size_t)(rbase+8) * Nld + col) = ul1;
            }
        }
    }
}

// ================= mma projection (128 rows/CTA, 128 threads) =================
#define PTRS 80
#define P_AH 0
#define P_AL 10240
#define P_BH 20480
#define P_BL 28160
#define P_STG 35840
#define P_DYN (2*P_STG)

__global__ __launch_bounds__(128)
void proj_mma(const bf16* __restrict__ Ah, const bf16* __restrict__ Al, int lda,
              const bf16* __restrict__ Wth, const bf16* __restrict__ Wtl,
              const float* __restrict__ bias,
              bf16* __restrict__ Chh, bf16* __restrict__ Chl, int K)
{
    extern __shared__ char psm[];
    const uint32_t sb = smem_u32(psm);
    const int tid = threadIdx.x, lane = tid & 31, w = tid >> 5;
    const int row0 = blockIdx.x * 128;
    const int nch = K / 32;

    auto load = [&](int c, int st) {
        const uint32_t s0 = sb + st * P_STG;
        const int k0 = c * 32;
        #pragma unroll
        for (int i = 0; i < 4; ++i) {
            int idx = tid + i * 128;
            int r = idx >> 2, cc = idx & 3;
            size_t g = (size_t)(row0 + r) * lda + k0 + cc * 8;
            cp16(s0 + P_AH + r * PTRS + cc * 16, Ah + g);
            cp16(s0 + P_AL + r * PTRS + cc * 16, Al + g);
        }
        #pragma unroll
        for (int i = 0; i < 3; ++i) {
            int idx = tid + i * 128;
            int r = idx >> 2, cc = idx & 3;
            size_t g = (size_t)r * K + k0 + cc * 8;
            cp16(s0 + P_BH + r * PTRS + cc * 16, Wth + g);
            cp16(s0 + P_BL + r * PTRS + cc * 16, Wtl + g);
        }
        cp_commit();
    };

    float acc[2][12][4];
    #pragma unroll
    for (int i = 0; i < 2; ++i)
        #pragma unroll
        for (int j = 0; j < 12; ++j)
            #pragma unroll
            for (int k = 0; k < 4; ++k) acc[i][j][k] = 0.f;

    load(0, 0);
    for (int c = 0; c < nch; ++c) {
        const int st = c & 1;
        if (c + 1 < nch) { load(c + 1, st ^ 1); cp_wait1(); }
        else             { cp_wait0(); }
        __syncthreads();
        const uint32_t s0 = sb + st * P_STG;

        #pragma unroll
        for (int ks = 0; ks < 2; ++ks) {
            uint32_t ahf[2][4], alf[2][4];
            #pragma unroll
            for (int mf = 0; mf < 2; ++mf) {
                uint32_t ad = s0 + (uint32_t)((w*32 + mf*16 + (lane & 15)) * PTRS + ks*32 + ((lane >> 4) << 4));
                ldm_x4(ad + P_AH, ahf[mf][0], ahf[mf][1], ahf[mf][2], ahf[mf][3]);
                ldm_x4(ad + P_AL, alf[mf][0], alf[mf][1], alf[mf][2], alf[mf][3]);
            }
            #pragma unroll
            for (int ng = 0; ng < 6; ++ng) {
                uint32_t bhf[4], blf[4];
                uint32_t bd = s0 + (uint32_t)((ng*16 + ((lane >> 4) << 3) + (lane & 7)) * PTRS
                                              + ks*32 + (((lane >> 3) & 1) << 4));
                ldm_x4(bd + P_BH, bhf[0], bhf[1], bhf[2], bhf[3]);
                ldm_x4(bd + P_BL, blf[0], blf[1], blf[2], blf[3]);
                #pragma unroll
                for (int mf = 0; mf < 2; ++mf) {
                    mma16816(acc[mf][2*ng],   ahf[mf][0], ahf[mf][1], ahf[mf][2], ahf[mf][3], bhf[0], bhf[1]);
                    mma16816(acc[mf][2*ng+1], ahf[mf][0], ahf[mf][1], ahf[mf][2], ahf[mf][3], bhf[2], bhf[3]);
                    mma16816(acc[mf][2*ng],   ahf[mf][0], ahf[mf][1], ahf[mf][2], ahf[mf][3], blf[0], blf[1]);
                    mma16816(acc[mf][2*ng+1], ahf[mf][0], ahf[mf][1], ahf[mf][2], ahf[mf][3], blf[2], blf[3]);
                    mma16816(acc[mf][2*ng],   alf[mf][0], alf[mf][1], alf[mf][2], alf[mf][3], bhf[0], bhf[1]);
                    mma16816(acc[mf][2*ng+1], alf[mf][0], alf[mf][1], alf[mf][2], alf[mf][3], bhf[2], bhf[3]);
                }
            }
        }
        __syncthreads();
    }

    const int rg = lane >> 2, cg = (lane & 3) * 2;
    #pragma unroll
    for (int mf = 0; mf < 2; ++mf) {
        const int r0 = row0 + w*32 + mf*16 + rg;
        #pragma unroll
        for (int nf = 0; nf < 12; ++nf) {
            const int col = nf * 8 + cg;
            const float2 bia = *(const float2*)(bias + col);
            float f0 = acc[mf][nf][0] + bia.x;
            float f1 = acc[mf][nf][1] + bia.y;
            float f2 = acc[mf][nf][2] + bia.x;
            float f3 = acc[mf][nf][3] + bia.y;
            unsigned uh0, ul0, uh1, ul1;
            pack2(f0, f1, uh0, ul0);
            pack2(f2, f3, uh1, ul1);
            *(unsigned*)(Chh + (size_t)r0 * QKVW + col)       = uh0;
            *(unsigned*)(Chh + (size_t)(r0+8) * QKVW + col)   = uh1;
            *(unsigned*)(Chl + (size_t)r0 * QKVW + col)       = ul0;
            *(unsigned*)(Chl + (size_t)(r0+8) * QKVW + col)   = ul1;
        }
    }
}

// ================= mma.sync flash attention: 64 q-rows/CTA, phase-batched (R11 config) =================
#define ATTN_SCALE 0.03125f   // 1/sqrt(1024)
#define ATRS 80
#define AQH 0
#define AQL 5120              // 64 rows x 80B
#define AKV0 10240
#define AKVSTG 20480
#define AOKH 0
#define AOKL 5120
#define AOVH 10240
#define AOVL 15360
#define ATTN_DYN 51200        // 10240 Q + 2x20480 KV

__global__ __launch_bounds__(128, 4)
void attn_mma(const bf16* __restrict__ qkvh, const bf16* __restrict__ qkvl,
              bf16* __restrict__ outh, bf16* __restrict__ outl)
{
    extern __shared__ char asmem[];
    const uint32_t sb = smem_u32(asmem);
    const int tid = threadIdx.x, lane = tid & 31, w = tid >> 5;   // 4 warps
    const int b = blockIdx.y;
    const int q0 = blockIdx.x * 64;
    const size_t base = (size_t)b * Ssz * QKVW;

    // stage Q (hi/lo): 64 rows x 4x16B chunks each
    #pragma unroll
    for (int i = 0; i < 2; ++i) {
        int idx = tid + i * 128;
        int r = idx >> 2, c = idx & 3;
        size_t g = base + (size_t)(q0 + r) * QKVW + c * 8;
        cp16(sb + AQH + r * ATRS + c * 16, qkvh + g);
        cp16(sb + AQL + r * ATRS + c * 16, qkvl + g);
    }
    cp_commit();
    // KV chunk 0 (64 keys)
    {
        const uint32_t s0 = sb + AKV0;
        #pragma unroll
        for (int i = 0; i < 2; ++i) {
            int idx = tid + i * 128;
            int r = idx >> 2, c = idx & 3;
            size_t gk = base + (size_t)r * QKVW + 32 + c * 8;
            cp16(s0 + AOKH + r * ATRS + c * 16, qkvh + gk);
            cp16(s0 + AOKL + r * ATRS + c * 16, qkvl + gk);
            cp16(s0 + AOVH + r * ATRS + c * 16, qkvh + gk + 32);
            cp16(s0 + AOVL + r * ATRS + c * 16, qkvl + gk + 32);
        }
        cp_commit();
    }
    cp_wait1();           // Q complete
    __syncthreads();

    // Q fragments: 16 rows per warp, [kslab][4]
    uint32_t qh[2][4], ql[2][4];
    #pragma unroll
    for (int ks = 0; ks < 2; ++ks) {
        uint32_t ad = sb + (uint32_t)((w * 16 + (lane & 15)) * ATRS + ks * 32 + ((lane >> 4) << 4));
        ldm_x4(ad + AQH, qh[ks][0], qh[ks][1], qh[ks][2], qh[ks][3]);
        ldm_x4(ad + AQL, ql[ks][0], ql[ks][1], ql[ks][2], ql[ks][3]);
    }

    float o[4][4];
    float lsum[2];
    lsum[0] = 0.f; lsum[1] = 0.f;
    #pragma unroll
    for (int n8 = 0; n8 < 4; ++n8)
        #pragma unroll
        for (int j = 0; j < 4; ++j) o[n8][j] = 0.f;

    const int krow  = ((lane >> 4) << 3) + (lane & 7);
    const int kcolb = (((lane >> 3) & 1) << 4);
    const int vrow  = ((lane >> 3) & 1) * 8 + (lane & 7);
    const int vcolb = ((lane >> 4) << 4);

    for (int c = 0; c < 16; ++c) {
        const int st = c & 1;
        if (c < 15) {
            const uint32_t s1 = sb + AKV0 + (st ^ 1) * AKVSTG;
            #pragma unroll
            for (int i = 0; i < 2; ++i) {
                int idx = tid + i * 128;
                int r = idx >> 2, cc = idx & 3;
                size_t gk = base + (size_t)((c + 1) * 64 + r) * QKVW + 32 + cc * 8;
                cp16(s1 + AOKH + r * ATRS + cc * 16, qkvh + gk);
                cp16(s1 + AOKL + r * ATRS + cc * 16, qkvl + gk);
                cp16(s1 + AOVH + r * ATRS + cc * 16, qkvh + gk + 32);
                cp16(s1 + AOVL + r * ATRS + cc * 16, qkvl + gk + 32);
            }
            cp_commit(); cp_wait1();
        } else cp_wait0();
        __syncthreads();

        const uint32_t kb = sb + AKV0 + st * AKVSTG;

        // ---- Phase A: S = Q K^T for ALL 4 groups (8 independent acc chains) ----
        float s[4][2][4];
        #pragma unroll
        for (int g = 0; g < 4; ++g)
            #pragma unroll
            for (int f = 0; f < 2; ++f)
                #pragma unroll
                for (int j = 0; j < 4; ++j) s[g][f][j] = 0.f;

        #pragma unroll
        for (int g = 0; g < 4; ++g) {
            #pragma unroll
            for (int ks = 0; ks < 2; ++ks) {
                uint32_t kh[4], kl[4];
                uint32_t ad = kb + (uint32_t)((g * 16 + krow) * ATRS + ks * 32 + kcolb);
                ldm_x4(ad + AOKH, kh[0], kh[1], kh[2], kh[3]);
                ldm_x4(ad + AOKL, kl[0], kl[1], kl[2], kl[3]);
                mma16816(s[g][0], qh[ks][0], qh[ks][1], qh[ks][2], qh[ks][3], kh[0], kh[1]);
                mma16816(s[g][1], qh[ks][0], qh[ks][1], qh[ks][2], qh[ks][3], kh[2], kh[3]);
                mma16816(s[g][0], qh[ks][0], qh[ks][1], qh[ks][2], qh[ks][3], kl[0], kl[1]);
                mma16816(s[g][1], qh[ks][0], qh[ks][1], qh[ks][2], qh[ks][3], kl[2], kl[3]);
                mma16816(s[g][0], ql[ks][0], ql[ks][1], ql[ks][2], ql[ks][3], kh[0], kh[1]);
                mma16816(s[g][1], ql[ks][0], ql[ks][1], ql[ks][2], ql[ks][3], kh[2], kh[3]);
            }
        }

        // ---- Phase B: exp + pack for ALL groups (batched MUFU/ALU) ----
        uint32_t ph[4][4], pl[4][4];
        #pragma unroll
        for (int g = 0; g < 4; ++g) {
            float p[2][4];
            #pragma unroll
            for (int f = 0; f < 2; ++f)
                #pragma unroll
                for (int j = 0; j < 4; ++j)
                    p[f][j] = __expf(s[g][f][j] * ATTN_SCALE);
            lsum[0] += p[0][0] + p[0][1] + p[1][0] + p[1][1];
            lsum[1] += p[0][2] + p[0][3] + p[1][2] + p[1][3];
            #pragma unroll
            for (int f = 0; f < 2; ++f) {
                pack2(p[f][0], p[f][1], ph[g][2*f],   pl[g][2*f]);
                pack2(p[f][2], p[f][3], ph[g][2*f+1], pl[g][2*f+1]);
            }
        }

        // ---- Phase C: O += P V for ALL groups ----
        #pragma unroll
        for (int g = 0; g < 4; ++g) {
            uint32_t vh[2][4], vl[2][4];
            #pragma unroll
            for (int nw = 0; nw < 2; ++nw) {
                uint32_t ad = kb + (uint32_t)((g * 16 + vrow) * ATRS + nw * 32 + vcolb);
                ldm_x4t(ad + AOVH, vh[nw][0], vh[nw][1], vh[nw][2], vh[nw][3]);
                ldm_x4t(ad + AOVL, vl[nw][0], vl[nw][1], vl[nw][2], vl[nw][3]);
            }
            #pragma unroll
            for (int n8 = 0; n8 < 4; ++n8) {
                const int nw = n8 >> 1, pr = (n8 & 1) * 2;
                mma16816(o[n8], ph[g][0], ph[g][1], ph[g][2], ph[g][3], vh[nw][pr], vh[nw][pr+1]);
                mma16816(o[n8], ph[g][0], ph[g][1], ph[g][2], ph[g][3], vl[nw][pr], vl[nw][pr+1]);
                mma16816(o[n8], pl[g][0], pl[g][1], pl[g][2], pl[g][3], vh[nw][pr], vh[nw][pr+1]);
            }
        }
        __syncthreads();
    }

    // ---- reduce row sums across the 4-lane column group, normalize, store ----
    #pragma unroll
    for (int hh = 0; hh < 2; ++hh) {
        float v = lsum[hh];
        v += __shfl_xor_sync(0xffffffffu, v, 1);
        v += __shfl_xor_sync(0xffffffffu, v, 2);
        lsum[hh] = 1.f / v;
    }
    const int rg = lane >> 2, cg = (lane & 3) * 2;
    const int r0 = q0 + w * 16 + rg;
    #pragma unroll
    for (int n8 = 0; n8 < 4; ++n8) {
        const int col = n8 * 8 + cg;
        float f0 = o[n8][0] * lsum[0];
        float f1 = o[n8][1] * lsum[0];
        float f2 = o[n8][2] * lsum[1];
        float f3 = o[n8][3] * lsum[1];
        size_t off0 = ((size_t)b * Ssz + r0) * Dsz + col;
        size_t off1 = off0 + (size_t)8 * Dsz;
        unsigned uh0, ul0, uh1, ul1;
        pack2(f0, f1, uh0, ul0);
        pack2(f2, f3, uh1, ul1);
        *(unsigned*)(outh + off0) = uh0;
        *(unsigned*)(outh + off1) = uh1;
        *(unsigned*)(outl + off0) = ul0;
        *(unsigned*)(outl + off1) = ul1;
    }
}

// ================= LayerNorm (512, eps=1e-3), warp-per-row, 4 rows/CTA =================
__global__ __launch_bounds__(128)
void ln_kernel(const float* __restrict__ y, const float* __restrict__ g,
               const float* __restrict__ be, float* __restrict__ x,
               bf16* __restrict__ xh, bf16* __restrict__ xl)
{
    const int warp = threadIdx.x >> 5, lane = threadIdx.x & 31;
    const int row = blockIdx.x * 4 + warp;
    const float* yr = y + (size_t)row * Dsz;

    float4 v[4];
    float sum = 0.f, sq = 0.f;
    #pragma unroll
    for (int i = 0; i < 4; ++i) {
        v[i] = *(const float4*)(yr + (lane + i * 32) * 4);
        sum += v[i].x + v[i].y + v[i].z + v[i].w;
        sq  += v[i].x*v[i].x + v[i].y*v[i].y + v[i].z*v[i].z + v[i].w*v[i].w;
    }
    #pragma unroll
    for (int o = 16; o > 0; o >>= 1) {
        sum += __shfl_xor_sync(0xffffffffu, sum, o);
        sq  += __shfl_xor_sync(0xffffffffu, sq,  o);
    }
    const float mean = sum * (1.f / (float)Dsz);
    const float var  = sq * (1.f / (float)Dsz) - mean * mean;
    const float r    = rsqrtf(var + 1e-3f);

    #pragma unroll
    for (int i = 0; i < 4; ++i) {
        const int d4 = (lane + i * 32) * 4;
        float4 gg = *(const float4*)(g + d4);
        float4 bb = *(const float4*)(be + d4);
        float4 out;
        out.x = (v[i].x - mean) * r * gg.x + bb.x;
        out.y = (v[i].y - mean) * r * gg.y + bb.y;
        out.z = (v[i].z - mean) * r * gg.z + bb.z;
        out.w = (v[i].w - mean) * r * gg.w + bb.w;
        *(float4*)(x + (size_t)row * Dsz + d4) = out;
        uint2 uh, ul;
        pack2(out.x, out.y, uh.x, ul.x);
        pack2(out.z, out.w, uh.y, ul.y);
        *(uint2*)(xh + (size_t)row * Dsz + d4) = uh;
        *(uint2*)(xl + (size_t)row * Dsz + d4) = ul;
    }
}

// ================= mean-pool + final dense + sigmoid =================
__global__ __launch_bounds__(256)
void final_kernel(const float* __restrict__ x, const float* __restrict__ Wf,
                  const float* __restrict__ bf_, float* __restrict__ out, int out_size)
{
    const int b = blockIdx.x;
    const float* xb = x + (size_t)b * Ssz * Dsz;
    float acc = 0.f;
    for (int i = threadIdx.x; i < (Ssz * Dsz) / 4; i += 256) {
        float4 v = *(const float4*)(xb + (size_t)i * 4);
        int d = (i * 4) & (Dsz - 1);
        acc += v.x * Wf[d] + v.y * Wf[d+1] + v.z * Wf[d+2] + v.w * Wf[d+3];
    }
    #pragma unroll
    for (int o = 16; o > 0; o >>= 1) acc += __shfl_down_sync(0xffffffffu, acc, o);
    __shared__ float ws[8];
    int warp = threadIdx.x >> 5, lane = threadIdx.x & 31;
    if (lane == 0) ws[warp] = acc;
    __syncthreads();
    if (threadIdx.x == 0) {
        float tot = 0.f;
        #pragma unroll
        for (int w = 0; w < 8; ++w) tot += ws[w];
        float logit = tot * (1.f / (float)Ssz) + bf_[0];
        if (b < out_size) out[b] = logit;
        if (Bsz + b < out_size) out[Bsz + b] = 1.f / (1.f + expf(-logit));
    }
}

// ================= orchestration =================
extern "C" void kernel_launch(void* const* d_in, const int* in_sizes, int n_in,
                              void* d_out, int out_size)
{
    const int*   tok = (const int*)  d_in[0];
    const float* emb = (const float*)d_in[1];
    const float* W0  = (const float*)d_in[2];
    const float* b0  = (const float*)d_in[3];
    const float* Wh  = (const float*)d_in[4];
    const float* bh  = (const float*)d_in[5];
    const float* Wo  = (const float*)d_in[6];
    const float* bo  = (const float*)d_in[7];
    const float* g1  = (const float*)d_in[8];
    const float* be1 = (const float*)d_in[9];
    const float* W1  = (const float*)d_in[10];
    const float* b1  = (const float*)d_in[11];
    const float* W2  = (const float*)d_in[12];
    const float* b2  = (const float*)d_in[13];
    const float* g2  = (const float*)d_in[14];
    const float* be2 = (const float*)d_in[15];
    const float* Wf  = (const float*)d_in[16];
    const float* bf_ = (const float*)d_in[17];
    float* out = (float*)d_out;

    float *x, *y;
    bf16 *qkvh, *qkvl, *xhh, *xhl, *xbh, *xbl, *xch, *xcl, *h1h, *h1l;
    bf16 *woth, *wotl, *w1th, *w1tl, *w2th, *w2tl, *w0th, *w0tl, *whth, *whtl;
    cudaGetSymbolAddress((void**)&x,    g_x);
    cudaGetSymbolAddress((void**)&y,    g_y);
    cudaGetSymbolAddress((void**)&qkvh, g_qkvh);
    cudaGetSymbolAddress((void**)&qkvl, g_qkvl);
    cudaGetSymbolAddress((void**)&xhh,  g_xhh);
    cudaGetSymbolAddress((void**)&xhl,  g_xhl);
    cudaGetSymbolAddress((void**)&xbh,  g_xbh);
    cudaGetSymbolAddress((void**)&xbl,  g_xbl);
    cudaGetSymbolAddress((void**)&xch,  g_xch);
    cudaGetSymbolAddress((void**)&xcl,  g_xcl);
    cudaGetSymbolAddress((void**)&h1h,  g_h1h);
    cudaGetSymbolAddress((void**)&h1l,  g_h1l);
    cudaGetSymbolAddress((void**)&woth, g_woth);
    cudaGetSymbolAddress((void**)&wotl, g_wotl);
    cudaGetSymbolAddress((void**)&w1th, g_w1th);
    cudaGetSymbolAddress((void**)&w1tl, g_w1tl);
    cudaGetSymbolAddress((void**)&w2th, g_w2th);
    cudaGetSymbolAddress((void**)&w2tl, g_w2tl);
    cudaGetSymbolAddress((void**)&w0th, g_w0th);
    cudaGetSymbolAddress((void**)&w0tl, g_w0tl);
    cudaGetSymbolAddress((void**)&whth, g_whth);
    cudaGetSymbolAddress((void**)&whtl, g_whtl);

    cudaFuncSetAttribute(gemm_mma<0>, cudaFuncAttributeMaxDynamicSharedMemorySize, GDYN);
    cudaFuncSetAttribute(gemm_mma<1>, cudaFuncAttributeMaxDynamicSharedMemorySize, GDYN);
    cudaFuncSetAttribute(attn_mma,    cudaFuncAttributeMaxDynamicSharedMemorySize, ATTN_DYN);
    cudaFuncSetAttribute(proj_mma,    cudaFuncAttributeMaxDynamicSharedMemorySize, P_DYN);

    {
        int64_t tot = (int64_t)Bsz * Ssz * Dsz / 2;
        embed_kernel<<<(unsigned)((tot + 255) / 256), 256>>>(tok, emb, x, xch, xcl);
    }

    // fused weight transpose + bf16 split (one launch)
    wsplit_all<<<WSP_TOTAL, 256>>>(Wo, W1, W2, W0, Wh,
                                   woth, wotl, w1th, w1tl, w2th, w2tl,
                                   w0th, w0tl, whth, whtl);

    const dim3 attn_grid(Ssz / 64, Bsz);         // (16, 32) = 512 CTAs
    const dim3 tc_wo(Dsz / GBN,  MROWS / GBM);   // (8, 256)
    const dim3 tc_f1(FFd / GBN,  MROWS / GBM);   // (32, 256)
    const dim3 tc_f2(Dsz / GBN,  MROWS / GBM);   // (8, 256)

    for (int l = 0; l < NBlk; ++l) {
        // head 0: D -> 96 (mma, reads post-LN2/embed hi/lo)
        proj_mma<<<MROWS/128, 128, P_DYN>>>(xch, xcl, Dsz,
            w0th + (size_t)l * QKVW * Dsz, w0tl + (size_t)l * QKVW * Dsz,
            b0 + (size_t)l * QKVW, qkvh, qkvl, Dsz);
        attn_mma<<<attn_grid, 128, ATTN_DYN>>>(qkvh, qkvl, xhh, xhl);

        // chained heads 1..15: DH -> 96
        for (int h = 1; h < Hh; ++h) {
            const size_t wo = ((size_t)l * (Hh - 1) + (h - 1)) * QKVW * DHd;
            proj_mma<<<MROWS/128, 128, P_DYN>>>(
                xhh + (size_t)(h - 1) * DHd, xhl + (size_t)(h - 1) * DHd, Dsz,
                whth + wo, whtl + wo,
                bh + ((size_t)l * (Hh - 1) + (h - 1)) * QKVW, qkvh, qkvl, DHd);
            attn_mma<<<attn_grid, 128, ATTN_DYN>>>(qkvh, qkvl,
                xhh + (size_t)h * DHd, xhl + (size_t)h * DHd);
        }

        // output projection + residual (mma), then LN1 (emit bf16)
        gemm_mma<0><<<tc_wo, 256, GDYN>>>(xhh, xhl,
            woth + (size_t)l * Dsz * Dsz, wotl + (size_t)l * Dsz * Dsz,
            bo + (size_t)l * Dsz, x, y, nullptr, nullptr, Dsz, Dsz);
        ln_kernel<<<MROWS/4, 128>>>(y, g1 + (size_t)l * Dsz, be1 + (size_t)l * Dsz,
                                    x, xbh, xbl);

        // FFN1 (mma, relu -> bf16 split)
        gemm_mma<1><<<tc_f1, 256, GDYN>>>(xbh, xbl,
            w1th + (size_t)l * FFd * Dsz, w1tl + (size_t)l * FFd * Dsz,
            b1 + (size_t)l * FFd, nullptr, nullptr, h1h, h1l, Dsz, FFd);

        // FFN2 (mma) + residual, then LN2 (emit bf16 for next layer head0)
        gemm_mma<0><<<tc_f2, 256, GDYN>>>(h1h, h1l,
            w2th + (size_t)l * Dsz * FFd, w2tl + (size_t)l * Dsz * FFd,
            b2 + (size_t)l * Dsz, x, y, nullptr, nullptr, FFd, Dsz);
        ln_kernel<<<MROWS/4, 128>>>(y, g2 + (size_t)l * Dsz, be2 + (size_t)l * Dsz,
                                    x, xch, xcl);
    }

    final_kernel<<<Bsz, 256>>>(x, Wf, bf_, out, out_size);
}

// round 17
// speedup vs baseline: 1.0687x; 1.0425x over previous
#include <cuda_runtime.h>
#include <cuda_bf16.h>
#include <math.h>
#include <stdint.h>

// Problem dims
#define Bsz   32
#define Ssz   1024
#define Dsz   512
#define Hh    16
#define NBlk  12
#define DHd   32
#define FFd   2048
#define MROWS (Bsz*Ssz)            // 32768
#define QKVW  96                   // 3*DHd
#define HROWS (MROWS/2)            // 16384 rows per batch-half

typedef __nv_bfloat16 bf16;

// ---------------- scratch (allocation-free: __device__ globals) ----------------
__device__ float g_x  [(size_t)MROWS*Dsz];
__device__ float g_y  [(size_t)MROWS*Dsz];
__device__ bf16  g_qkvh[(size_t)MROWS*QKVW];
__device__ bf16  g_qkvl[(size_t)MROWS*QKVW];
__device__ bf16  g_xhh[(size_t)MROWS*Dsz];
__device__ bf16  g_xhl[(size_t)MROWS*Dsz];
__device__ bf16  g_xbh[(size_t)MROWS*Dsz];
__device__ bf16  g_xbl[(size_t)MROWS*Dsz];
__device__ bf16  g_xch[(size_t)MROWS*Dsz];
__device__ bf16  g_xcl[(size_t)MROWS*Dsz];
__device__ bf16  g_h1h[(size_t)MROWS*FFd];
__device__ bf16  g_h1l[(size_t)MROWS*FFd];
__device__ bf16  g_woth[(size_t)NBlk*Dsz*Dsz];
__device__ bf16  g_wotl[(size_t)NBlk*Dsz*Dsz];
__device__ bf16  g_w1th[(size_t)NBlk*FFd*Dsz];
__device__ bf16  g_w1tl[(size_t)NBlk*FFd*Dsz];
__device__ bf16  g_w2th[(size_t)NBlk*Dsz*FFd];
__device__ bf16  g_w2tl[(size_t)NBlk*Dsz*FFd];
__device__ bf16  g_w0th[(size_t)NBlk*QKVW*Dsz];
__device__ bf16  g_w0tl[(size_t)NBlk*QKVW*Dsz];
__device__ bf16  g_whth[(size_t)NBlk*(Hh-1)*QKVW*DHd];
__device__ bf16  g_whtl[(size_t)NBlk*(Hh-1)*QKVW*DHd];

// ================= low-level helpers =================
__device__ __forceinline__ uint32_t smem_u32(const void* p) {
    uint32_t a;
    asm("{ .reg .u64 t; cvta.to.shared.u64 t, %1; cvt.u32.u64 %0, t; }" : "=r"(a) : "l"(p));
    return a;
}
static __device__ __forceinline__ uint32_t swz128(uint32_t off) { return off ^ ((off >> 3) & 0x70u); }

__device__ __forceinline__ void cp16(uint32_t smem, const void* gmem) {
    asm volatile("cp.async.cg.shared.global [%0], [%1], 16;" :: "r"(smem), "l"(gmem));
}
__device__ __forceinline__ void cp_commit() { asm volatile("cp.async.commit_group;"); }
__device__ __forceinline__ void cp_wait0() { asm volatile("cp.async.wait_group 0;"); }
__device__ __forceinline__ void cp_wait1() { asm volatile("cp.async.wait_group 1;"); }

__device__ __forceinline__ void ldm_x4(uint32_t addr, uint32_t& r0, uint32_t& r1, uint32_t& r2, uint32_t& r3) {
    asm volatile("ldmatrix.sync.aligned.m8n8.x4.shared.b16 {%0,%1,%2,%3}, [%4];"
                 : "=r"(r0), "=r"(r1), "=r"(r2), "=r"(r3) : "r"(addr));
}
__device__ __forceinline__ void ldm_x4t(uint32_t addr, uint32_t& r0, uint32_t& r1, uint32_t& r2, uint32_t& r3) {
    asm volatile("ldmatrix.sync.aligned.m8n8.x4.trans.shared.b16 {%0,%1,%2,%3}, [%4];"
                 : "=r"(r0), "=r"(r1), "=r"(r2), "=r"(r3) : "r"(addr));
}
__device__ __forceinline__ void mma16816(float* c, uint32_t a0, uint32_t a1, uint32_t a2, uint32_t a3,
                                         uint32_t b0, uint32_t b1) {
    asm volatile("mma.sync.aligned.m16n8k16.row.col.f32.bf16.bf16.f32 "
                 "{%0,%1,%2,%3}, {%4,%5,%6,%7}, {%8,%9}, {%0,%1,%2,%3};"
                 : "+f"(c[0]), "+f"(c[1]), "+f"(c[2]), "+f"(c[3])
                 : "r"(a0), "r"(a1), "r"(a2), "r"(a3), "r"(b0), "r"(b1));
}
__device__ __forceinline__ void pack2(float a, float b, unsigned& uh, unsigned& ul) {
    asm("cvt.rn.bf16x2.f32 %0, %1, %2;" : "=r"(uh) : "f"(b), "f"(a));
    float fa = __uint_as_float(uh << 16);
    float fb = __uint_as_float(uh & 0xffff0000u);
    asm("cvt.rn.bf16x2.f32 %0, %1, %2;" : "=r"(ul) : "f"(b - fb), "f"(a - fa));
}

// ================= embedding + positional encoding (fp32 + hi/lo) =================
__global__ void embed_kernel(const int* __restrict__ tok,
                             const float* __restrict__ emb,
                             float* __restrict__ x,
                             bf16* __restrict__ xh, bf16* __restrict__ xl)
{
    int64_t i2 = ((int64_t)blockIdx.x * blockDim.x + threadIdx.x) * 2;
    if (i2 >= (int64_t)Bsz * Ssz * Dsz) return;
    float vv[2];
    #pragma unroll
    for (int u = 0; u < 2; ++u) {
        int64_t i = i2 + u;
        int d      = (int)(i & (Dsz - 1));
        int64_t bs = i >> 9;
        int s      = (int)(bs & (Ssz - 1));
        int t      = tok[bs];
        int j      = d >> 1;
        float e    = (2.0f * (float)j) / (float)Dsz;
        float freq = expf(-e * 9.210340371976184f);
        float ang  = (float)s * freq;
        float p    = (d & 1) ? cosf(ang) : sinf(ang);
        vv[u] = emb[(int64_t)t * Dsz + d] + p;
        x[i] = vv[u];
    }
    unsigned uh, ul;
    pack2(vv[0], vv[1], uh, ul);
    *(unsigned*)(xh + i2) = uh;
    *(unsigned*)(xl + i2) = ul;
}

// ================= fused weight transpose + bf16 split (single launch) =================
#define WSP_WO_END  3072
#define WSP_W1_END  (WSP_WO_END + 12288)
#define WSP_W2_END  (WSP_W1_END + 12288)
#define WSP_W0_END  (WSP_W2_END + 576)
#define WSP_TOTAL   (WSP_W0_END + 540)

__global__ __launch_bounds__(256)
void wsplit_all(const float* __restrict__ Wo, const float* __restrict__ W1,
                const float* __restrict__ W2, const float* __restrict__ W0,
                const float* __restrict__ Wh,
                bf16* __restrict__ woth, bf16* __restrict__ wotl,
                bf16* __restrict__ w1th, bf16* __restrict__ w1tl,
                bf16* __restrict__ w2th, bf16* __restrict__ w2tl,
                bf16* __restrict__ w0th, bf16* __restrict__ w0tl,
                bf16* __restrict__ whth, bf16* __restrict__ whtl)
{
    __shared__ float t[32][33];
    int b = blockIdx.x;
    const float* W; bf16 *Th, *Tl;
    int K, N, z, nb, kb;
    if (b < WSP_WO_END) {
        z = b >> 8; int r = b & 255; nb = r & 15; kb = r >> 4;
        W = Wo; Th = woth; Tl = wotl; K = Dsz; N = Dsz;
    } else if (b < WSP_W1_END) {
        int i = b - WSP_WO_END; z = i >> 10; int r = i & 1023; nb = r & 63; kb = r >> 6;
        W = W1; Th = w1th; Tl = w1tl; K = Dsz; N = FFd;
    } else if (b < WSP_W2_END) {
        int i = b - WSP_W1_END; z = i >> 10; int r = i & 1023; nb = r & 15; kb = r >> 4;
        W = W2; Th = w2th; Tl = w2tl; K = FFd; N = Dsz;
    } else if (b < WSP_W0_END) {
        int i = b - WSP_W2_END; z = i / 48; int r = i % 48; nb = r % 3; kb = r / 3;
        W = W0; Th = w0th; Tl = w0tl; K = Dsz; N = QKVW;
    } else {
        int i = b - WSP_W0_END; z = i / 3; nb = i % 3; kb = 0;
        W = Wh; Th = whth; Tl = whtl; K = DHd; N = QKVW;
    }
    const float* Wz = W + (size_t)z * K * N;
    bf16* Thz = Th + (size_t)z * K * N;
    bf16* Tlz = Tl + (size_t)z * K * N;
    int n0 = nb * 32, k0 = kb * 32;
    int tx = threadIdx.x & 31, ty = threadIdx.x >> 5;
    #pragma unroll
    for (int i = 0; i < 4; ++i)
        t[ty + i*8][tx] = Wz[(size_t)(k0 + ty + i*8) * N + n0 + tx];
    __syncthreads();
    #pragma unroll
    for (int i = 0; i < 4; ++i) {
        float v = t[tx][ty + i*8];
        bf16 h = __float2bfloat16(v);
        bf16 lo = __float2bfloat16(v - __bfloat162float(h));
        size_t o = (size_t)(n0 + ty + i*8) * K + k0 + tx;
        Thz[o] = h; Tlz[o] = lo;
    }
}

// ================= mma.sync bf16-split GEMM (big GEMMs), 128x64 tile, 2 CTAs/SM =================
#define GBM 128
#define GBN 64
#define GBK 64
#define ST_AH 0
#define ST_AL 16384
#define ST_BH 32768
#define ST_BL 40960
#define STAGE_BYTES 49152
#define GDYN (2*STAGE_BYTES)

template<int EPI>
__global__ __launch_bounds__(256, 2)
void gemm_mma(const bf16* __restrict__ Ah, const bf16* __restrict__ Al,
              const bf16* __restrict__ Bh, const bf16* __restrict__ Bl,
              const float* __restrict__ bias,
              const float* __restrict__ resid,
              float* __restrict__ Cf,
              bf16* __restrict__ Chh, bf16* __restrict__ Chl,
              int K, int Nld)
{
    extern __shared__ char dsm[];
    const uint32_t sb = smem_u32(dsm);

    const int tid  = threadIdx.x;
    const int lane = tid & 31;
    const int w    = tid >> 5;
    const int wm   = w >> 1;
    const int wn   = w & 1;
    const int row0 = blockIdx.y * GBM;
    const int col0 = blockIdx.x * GBN;

    float acc[2][4][4];
    #pragma unroll
    for (int i = 0; i < 2; ++i)
        #pragma unroll
        for (int j = 0; j < 4; ++j)
            #pragma unroll
            for (int k = 0; k < 4; ++k) acc[i][j][k] = 0.f;

    const int nchunks = K / GBK;

    auto load_stage = [&](int c, int st) {
        const uint32_t s0 = sb + st * STAGE_BYTES;
        const size_t kofs = (size_t)c * GBK;
        const int lr = tid >> 3, lc = tid & 7;
        #pragma unroll
        for (int i = 0; i < 4; ++i) {
            int r = lr + i * 32;
            uint32_t so = swz128((uint32_t)(r * 128 + lc * 16));
            size_t g = (size_t)(row0 + r) * K + kofs + lc * 8;
            cp16(s0 + ST_AH + so, Ah + g);
            cp16(s0 + ST_AL + so, Al + g);
        }
        #pragma unroll
        for (int i = 0; i < 2; ++i) {
            int r = lr + i * 32;
            uint32_t so = swz128((uint32_t)(r * 128 + lc * 16));
            size_t g = (size_t)(col0 + r) * K + kofs + lc * 8;
            cp16(s0 + ST_BH + so, Bh + g);
            cp16(s0 + ST_BL + so, Bl + g);
        }
        cp_commit();
    };

    load_stage(0, 0);

    for (int c = 0; c < nchunks; ++c) {
        const int st = c & 1;
        if (c + 1 < nchunks) { load_stage(c + 1, st ^ 1); cp_wait1(); }
        else                 { cp_wait0(); }
        __syncthreads();

        const uint32_t s0 = sb + st * STAGE_BYTES;
        const int arow  = wm * 32 + (lane & 15);
        const int acolb = (lane >> 4) << 4;
        const int bcolb = ((lane >> 3) & 1) << 4;

        #pragma unroll
        for (int slab = 0; slab < 4; ++slab) {
            const int kb = slab * 32;
            uint32_t ah[2][4], al[2][4], bh[2][4], bl[2][4];
            #pragma unroll
            for (int mf = 0; mf < 2; ++mf) {
                uint32_t ao = swz128((uint32_t)((arow + mf*16) * 128 + kb + acolb));
                ldm_x4(s0 + ST_AH + ao, ah[mf][0], ah[mf][1], ah[mf][2], ah[mf][3]);
                ldm_x4(s0 + ST_AL + ao, al[mf][0], al[mf][1], al[mf][2], al[mf][3]);
            }
            #pragma unroll
            for (int ng = 0; ng < 2; ++ng) {
                int nrow = wn * 32 + ng * 16 + ((lane >> 4) << 3) + (lane & 7);
                uint32_t bo = swz128((uint32_t)(nrow * 128 + kb + bcolb));
                ldm_x4(s0 + ST_BH + bo, bh[ng][0], bh[ng][1], bh[ng][2], bh[ng][3]);
                ldm_x4(s0 + ST_BL + bo, bl[ng][0], bl[ng][1], bl[ng][2], bl[ng][3]);
            }
            #pragma unroll
            for (int mf = 0; mf < 2; ++mf) {
                #pragma unroll
                for (int ng = 0; ng < 2; ++ng) {
                    mma16816(acc[mf][2*ng],   ah[mf][0], ah[mf][1], ah[mf][2], ah[mf][3], bh[ng][0], bh[ng][1]);
                    mma16816(acc[mf][2*ng+1], ah[mf][0], ah[mf][1], ah[mf][2], ah[mf][3], bh[ng][2], bh[ng][3]);
                    mma16816(acc[mf][2*ng],   ah[mf][0], ah[mf][1], ah[mf][2], ah[mf][3], bl[ng][0], bl[ng][1]);
                    mma16816(acc[mf][2*ng+1], ah[mf][0], ah[mf][1], ah[mf][2], ah[mf][3], bl[ng][2], bl[ng][3]);
                    mma16816(acc[mf][2*ng],   al[mf][0], al[mf][1], al[mf][2], al[mf][3], bh[ng][0], bh[ng][1]);
                    mma16816(acc[mf][2*ng+1], al[mf][0], al[mf][1], al[mf][2], al[mf][3], bh[ng][2], bh[ng][3]);
                }
            }
        }
        __syncthreads();
    }

    const int rg = lane >> 2;
    const int cg = (lane & 3) * 2;
    #pragma unroll
    for (int mf = 0; mf < 2; ++mf) {
        const int rbase = row0 + wm*32 + mf*16 + rg;
        #pragma unroll
        for (int nf = 0; nf < 4; ++nf) {
            const int col = col0 + wn*32 + nf*8 + cg;
            const float2 bia = *(const float2*)(bias + col);
            float f0 = acc[mf][nf][0] + bia.x;
            float f1 = acc[mf][nf][1] + bia.y;
            float f2 = acc[mf][nf][2] + bia.x;
            float f3 = acc[mf][nf][3] + bia.y;
            if (EPI == 0) {
                const float2 r0v = *(const float2*)(resid + (size_t)rbase * Nld + col);
                const float2 r1v = *(const float2*)(resid + (size_t)(rbase+8) * Nld + col);
                *(float2*)(Cf + (size_t)rbase * Nld + col)     = make_float2(f0 + r0v.x, f1 + r0v.y);
                *(float2*)(Cf + (size_t)(rbase+8) * Nld + col) = make_float2(f2 + r1v.x, f3 + r1v.y);
            } else {
                f0 = fmaxf(f0, 0.f); f1 = fmaxf(f1, 0.f);
                f2 = fmaxf(f2, 0.f); f3 = fmaxf(f3, 0.f);
                unsigned uh0, ul0, uh1, ul1;
                pack2(f0, f1, uh0, ul0);
                pack2(f2, f3, uh1, ul1);
                *(unsigned*)(Chh + (size_t)rbase * Nld + col)     = uh0;
                *(unsigned*)(Chh + (size_t)(rbase+8) * Nld + col) = uh1;
                *(unsigned*)(Chl + (size_t)rbase * Nld + col)     = ul0;
                *(unsigned*)(Chl + (size_t)(rbase+8) * Nld + col) = ul1;
            }
        }
    }
}

// ================= mma projection (128 rows/CTA, 128 threads) =================
#define PTRS 80
#define P_AH 0
#define P_AL 10240
#define P_BH 20480
#define P_BL 28160
#define P_STG 35840
#define P_DYN (2*P_STG)

__global__ __launch_bounds__(128)
void proj_mma(const bf16* __restrict__ Ah, const bf16* __restrict__ Al, int lda,
              const bf16* __restrict__ Wth, const bf16* __restrict__ Wtl,
              const float* __restrict__ bias,
              bf16* __restrict__ Chh, bf16* __restrict__ Chl, int K)
{
    extern __shared__ char psm[];
    const uint32_t sb = smem_u32(psm);
    const int tid = threadIdx.x, lane = tid & 31, w = tid >> 5;
    const int row0 = blockIdx.x * 128;
    const int nch = K / 32;

    auto load = [&](int c, int st) {
        const uint32_t s0 = sb + st * P_STG;
        const int k0 = c * 32;
        #pragma unroll
        for (int i = 0; i < 4; ++i) {
            int idx = tid + i * 128;
            int r = idx >> 2, cc = idx & 3;
            size_t g = (size_t)(row0 + r) * lda + k0 + cc * 8;
            cp16(s0 + P_AH + r * PTRS + cc * 16, Ah + g);
            cp16(s0 + P_AL + r * PTRS + cc * 16, Al + g);
        }
        #pragma unroll
        for (int i = 0; i < 3; ++i) {
            int idx = tid + i * 128;
            int r = idx >> 2, cc = idx & 3;
            size_t g = (size_t)r * K + k0 + cc * 8;
            cp16(s0 + P_BH + r * PTRS + cc * 16, Wth + g);
            cp16(s0 + P_BL + r * PTRS + cc * 16, Wtl + g);
        }
        cp_commit();
    };

    float acc[2][12][4];
    #pragma unroll
    for (int i = 0; i < 2; ++i)
        #pragma unroll
        for (int j = 0; j < 12; ++j)
            #pragma unroll
            for (int k = 0; k < 4; ++k) acc[i][j][k] = 0.f;

    load(0, 0);
    for (int c = 0; c < nch; ++c) {
        const int st = c & 1;
        if (c + 1 < nch) { load(c + 1, st ^ 1); cp_wait1(); }
        else             { cp_wait0(); }
        __syncthreads();
        const uint32_t s0 = sb + st * P_STG;

        #pragma unroll
        for (int ks = 0; ks < 2; ++ks) {
            uint32_t ahf[2][4], alf[2][4];
            #pragma unroll
            for (int mf = 0; mf < 2; ++mf) {
                uint32_t ad = s0 + (uint32_t)((w*32 + mf*16 + (lane & 15)) * PTRS + ks*32 + ((lane >> 4) << 4));
                ldm_x4(ad + P_AH, ahf[mf][0], ahf[mf][1], ahf[mf][2], ahf[mf][3]);
                ldm_x4(ad + P_AL, alf[mf][0], alf[mf][1], alf[mf][2], alf[mf][3]);
            }
            #pragma unroll
            for (int ng = 0; ng < 6; ++ng) {
                uint32_t bhf[4], blf[4];
                uint32_t bd = s0 + (uint32_t)((ng*16 + ((lane >> 4) << 3) + (lane & 7)) * PTRS
                                              + ks*32 + (((lane >> 3) & 1) << 4));
                ldm_x4(bd + P_BH, bhf[0], bhf[1], bhf[2], bhf[3]);
                ldm_x4(bd + P_BL, blf[0], blf[1], blf[2], blf[3]);
                #pragma unroll
                for (int mf = 0; mf < 2; ++mf) {
                    mma16816(acc[mf][2*ng],   ahf[mf][0], ahf[mf][1], ahf[mf][2], ahf[mf][3], bhf[0], bhf[1]);
                    mma16816(acc[mf][2*ng+1], ahf[mf][0], ahf[mf][1], ahf[mf][2], ahf[mf][3], bhf[2], bhf[3]);
                    mma16816(acc[mf][2*ng],   ahf[mf][0], ahf[mf][1], ahf[mf][2], ahf[mf][3], blf[0], blf[1]);
                    mma16816(acc[mf][2*ng+1], ahf[mf][0], ahf[mf][1], ahf[mf][2], ahf[mf][3], blf[2], blf[3]);
                    mma16816(acc[mf][2*ng],   alf[mf][0], alf[mf][1], alf[mf][2], alf[mf][3], bhf[0], bhf[1]);
                    mma16816(acc[mf][2*ng+1], alf[mf][0], alf[mf][1], alf[mf][2], alf[mf][3], bhf[2], bhf[3]);
                }
            }
        }
        __syncthreads();
    }

    const int rg = lane >> 2, cg = (lane & 3) * 2;
    #pragma unroll
    for (int mf = 0; mf < 2; ++mf) {
        const int r0 = row0 + w*32 + mf*16 + rg;
        #pragma unroll
        for (int nf = 0; nf < 12; ++nf) {
            const int col = nf * 8 + cg;
            const float2 bia = *(const float2*)(bias + col);
            float f0 = acc[mf][nf][0] + bia.x;
            float f1 = acc[mf][nf][1] + bia.y;
            float f2 = acc[mf][nf][2] + bia.x;
            float f3 = acc[mf][nf][3] + bia.y;
            unsigned uh0, ul0, uh1, ul1;
            pack2(f0, f1, uh0, ul0);
            pack2(f2, f3, uh1, ul1);
            *(unsigned*)(Chh + (size_t)r0 * QKVW + col)       = uh0;
            *(unsigned*)(Chh + (size_t)(r0+8) * QKVW + col)   = uh1;
            *(unsigned*)(Chl + (size_t)r0 * QKVW + col)       = ul0;
            *(unsigned*)(Chl + (size_t)(r0+8) * QKVW + col)   = ul1;
        }
    }
}

// ================= mma.sync flash attention: 64 q-rows/CTA, phase-batched =================
#define ATTN_SCALE 0.03125f   // 1/sqrt(1024)
#define ATRS 80
#define AQH 0
#define AQL 5120
#define AKV0 10240
#define AKVSTG 20480
#define AOKH 0
#define AOKL 5120
#define AOVH 10240
#define AOVL 15360
#define ATTN_DYN 51200

__global__ __launch_bounds__(128, 4)
void attn_mma(const bf16* __restrict__ qkvh, const bf16* __restrict__ qkvl,
              bf16* __restrict__ outh, bf16* __restrict__ outl)
{
    extern __shared__ char asmem[];
    const uint32_t sb = smem_u32(asmem);
    const int tid = threadIdx.x, lane = tid & 31, w = tid >> 5;
    const int b = blockIdx.y;
    const int q0 = blockIdx.x * 64;
    const size_t base = (size_t)b * Ssz * QKVW;

    #pragma unroll
    for (int i = 0; i < 2; ++i) {
        int idx = tid + i * 128;
        int r = idx >> 2, c = idx & 3;
        size_t g = base + (size_t)(q0 + r) * QKVW + c * 8;
        cp16(sb + AQH + r * ATRS + c * 16, qkvh + g);
        cp16(sb + AQL + r * ATRS + c * 16, qkvl + g);
    }
    cp_commit();
    {
        const uint32_t s0 = sb + AKV0;
        #pragma unroll
        for (int i = 0; i < 2; ++i) {
            int idx = tid + i * 128;
            int r = idx >> 2, c = idx & 3;
            size_t gk = base + (size_t)r * QKVW + 32 + c * 8;
            cp16(s0 + AOKH + r * ATRS + c * 16, qkvh + gk);
            cp16(s0 + AOKL + r * ATRS + c * 16, qkvl + gk);
            cp16(s0 + AOVH + r * ATRS + c * 16, qkvh + gk + 32);
            cp16(s0 + AOVL + r * ATRS + c * 16, qkvl + gk + 32);
        }
        cp_commit();
    }
    cp_wait1();
    __syncthreads();

    uint32_t qh[2][4], ql[2][4];
    #pragma unroll
    for (int ks = 0; ks < 2; ++ks) {
        uint32_t ad = sb + (uint32_t)((w * 16 + (lane & 15)) * ATRS + ks * 32 + ((lane >> 4) << 4));
        ldm_x4(ad + AQH, qh[ks][0], qh[ks][1], qh[ks][2], qh[ks][3]);
        ldm_x4(ad + AQL, ql[ks][0], ql[ks][1], ql[ks][2], ql[ks][3]);
    }

    float o[4][4];
    float lsum[2];
    lsum[0] = 0.f; lsum[1] = 0.f;
    #pragma unroll
    for (int n8 = 0; n8 < 4; ++n8)
        #pragma unroll
        for (int j = 0; j < 4; ++j) o[n8][j] = 0.f;

    const int krow  = ((lane >> 4) << 3) + (lane & 7);
    const int kcolb = (((lane >> 3) & 1) << 4);
    const int vrow  = ((lane >> 3) & 1) * 8 + (lane & 7);
    const int vcolb = ((lane >> 4) << 4);

    for (int c = 0; c < 16; ++c) {
        const int st = c & 1;
        if (c < 15) {
            const uint32_t s1 = sb + AKV0 + (st ^ 1) * AKVSTG;
            #pragma unroll
            for (int i = 0; i < 2; ++i) {
                int idx = tid + i * 128;
                int r = idx >> 2, cc = idx & 3;
                size_t gk = base + (size_t)((c + 1) * 64 + r) * QKVW + 32 + cc * 8;
                cp16(s1 + AOKH + r * ATRS + cc * 16, qkvh + gk);
                cp16(s1 + AOKL + r * ATRS + cc * 16, qkvl + gk);
                cp16(s1 + AOVH + r * ATRS + cc * 16, qkvh + gk + 32);
                cp16(s1 + AOVL + r * ATRS + cc * 16, qkvl + gk + 32);
            }
            cp_commit(); cp_wait1();
        } else cp_wait0();
        __syncthreads();

        const uint32_t kb = sb + AKV0 + st * AKVSTG;

        float s[4][2][4];
        #pragma unroll
        for (int g = 0; g < 4; ++g)
            #pragma unroll
            for (int f = 0; f < 2; ++f)
                #pragma unroll
                for (int j = 0; j < 4; ++j) s[g][f][j] = 0.f;

        #pragma unroll
        for (int g = 0; g < 4; ++g) {
            #pragma unroll
            for (int ks = 0; ks < 2; ++ks) {
                uint32_t kh[4], kl[4];
                uint32_t ad = kb + (uint32_t)((g * 16 + krow) * ATRS + ks * 32 + kcolb);
                ldm_x4(ad + AOKH, kh[0], kh[1], kh[2], kh[3]);
                ldm_x4(ad + AOKL, kl[0], kl[1], kl[2], kl[3]);
                mma16816(s[g][0], qh[ks][0], qh[ks][1], qh[ks][2], qh[ks][3], kh[0], kh[1]);
                mma16816(s[g][1], qh[ks][0], qh[ks][1], qh[ks][2], qh[ks][3], kh[2], kh[3]);
                mma16816(s[g][0], qh[ks][0], qh[ks][1], qh[ks][2], qh[ks][3], kl[0], kl[1]);
                mma16816(s[g][1], qh[ks][0], qh[ks][1], qh[ks][2], qh[ks][3], kl[2], kl[3]);
                mma16816(s[g][0], ql[ks][0], ql[ks][1], ql[ks][2], ql[ks][3], kh[0], kh[1]);
                mma16816(s[g][1], ql[ks][0], ql[ks][1], ql[ks][2], ql[ks][3], kh[2], kh[3]);
            }
        }

        uint32_t ph[4][4], pl[4][4];
        #pragma unroll
        for (int g = 0; g < 4; ++g) {
            float p[2][4];
            #pragma unroll
            for (int f = 0; f < 2; ++f)
                #pragma unroll
                for (int j = 0; j < 4; ++j)
                    p[f][j] = __expf(s[g][f][j] * ATTN_SCALE);
            lsum[0] += p[0][0] + p[0][1] + p[1][0] + p[1][1];
            lsum[1] += p[0][2] + p[0][3] + p[1][2] + p[1][3];
            #pragma unroll
            for (int f = 0; f < 2; ++f) {
                pack2(p[f][0], p[f][1], ph[g][2*f],   pl[g][2*f]);
                pack2(p[f][2], p[f][3], ph[g][2*f+1], pl[g][2*f+1]);
            }
        }

        #pragma unroll
        for (int g = 0; g < 4; ++g) {
            uint32_t vh[2][4], vl[2][4];
            #pragma unroll
            for (int nw = 0; nw < 2; ++nw) {
                uint32_t ad = kb + (uint32_t)((g * 16 + vrow) * ATRS + nw * 32 + vcolb);
                ldm_x4t(ad + AOVH, vh[nw][0], vh[nw][1], vh[nw][2], vh[nw][3]);
                ldm_x4t(ad + AOVL, vl[nw][0], vl[nw][1], vl[nw][2], vl[nw][3]);
            }
            #pragma unroll
            for (int n8 = 0; n8 < 4; ++n8) {
                const int nw = n8 >> 1, pr = (n8 & 1) * 2;
                mma16816(o[n8], ph[g][0], ph[g][1], ph[g][2], ph[g][3], vh[nw][pr], vh[nw][pr+1]);
                mma16816(o[n8], ph[g][0], ph[g][1], ph[g][2], ph[g][3], vl[nw][pr], vl[nw][pr+1]);
                mma16816(o[n8], pl[g][0], pl[g][1], pl[g][2], pl[g][3], vh[nw][pr], vh[nw][pr+1]);
            }
        }
        __syncthreads();
    }

    #pragma unroll
    for (int hh = 0; hh < 2; ++hh) {
        float v = lsum[hh];
        v += __shfl_xor_sync(0xffffffffu, v, 1);
        v += __shfl_xor_sync(0xffffffffu, v, 2);
        lsum[hh] = 1.f / v;
    }
    const int rg = lane >> 2, cg = (lane & 3) * 2;
    const int r0 = q0 + w * 16 + rg;
    #pragma unroll
    for (int n8 = 0; n8 < 4; ++n8) {
        const int col = n8 * 8 + cg;
        float f0 = o[n8][0] * lsum[0];
        float f1 = o[n8][1] * lsum[0];
        float f2 = o[n8][2] * lsum[1];
        float f3 = o[n8][3] * lsum[1];
        size_t off0 = ((size_t)b * Ssz + r0) * Dsz + col;
        size_t off1 = off0 + (size_t)8 * Dsz;
        unsigned uh0, ul0, uh1, ul1;
        pack2(f0, f1, uh0, ul0);
        pack2(f2, f3, uh1, ul1);
        *(unsigned*)(outh + off0) = uh0;
        *(unsigned*)(outh + off1) = uh1;
        *(unsigned*)(outl + off0) = ul0;
        *(unsigned*)(outl + off1) = ul1;
    }
}

// ================= LayerNorm (512, eps=1e-3), warp-per-row, 4 rows/CTA =================
__global__ __launch_bounds__(128)
void ln_kernel(const float* __restrict__ y, const float* __restrict__ g,
               const float* __restrict__ be, float* __restrict__ x,
               bf16* __restrict__ xh, bf16* __restrict__ xl)
{
    const int warp = threadIdx.x >> 5, lane = threadIdx.x & 31;
    const int row = blockIdx.x * 4 + warp;
    const float* yr = y + (size_t)row * Dsz;

    float4 v[4];
    float sum = 0.f, sq = 0.f;
    #pragma unroll
    for (int i = 0; i < 4; ++i) {
        v[i] = *(const float4*)(yr + (lane + i * 32) * 4);
        sum += v[i].x + v[i].y + v[i].z + v[i].w;
        sq  += v[i].x*v[i].x + v[i].y*v[i].y + v[i].z*v[i].z + v[i].w*v[i].w;
    }
    #pragma unroll
    for (int o = 16; o > 0; o >>= 1) {
        sum += __shfl_xor_sync(0xffffffffu, sum, o);
        sq  += __shfl_xor_sync(0xffffffffu, sq,  o);
    }
    const float mean = sum * (1.f / (float)Dsz);
    const float var  = sq * (1.f / (float)Dsz) - mean * mean;
    const float r    = rsqrtf(var + 1e-3f);

    #pragma unroll
    for (int i = 0; i < 4; ++i) {
        const int d4 = (lane + i * 32) * 4;
        float4 gg = *(const float4*)(g + d4);
        float4 bb = *(const float4*)(be + d4);
        float4 out;
        out.x = (v[i].x - mean) * r * gg.x + bb.x;
        out.y = (v[i].y - mean) * r * gg.y + bb.y;
        out.z = (v[i].z - mean) * r * gg.z + bb.z;
        out.w = (v[i].w - mean) * r * gg.w + bb.w;
        *(float4*)(x + (size_t)row * Dsz + d4) = out;
        uint2 uh, ul;
        pack2(out.x, out.y, uh.x, ul.x);
        pack2(out.z, out.w, uh.y, ul.y);
        *(uint2*)(xh + (size_t)row * Dsz + d4) = uh;
        *(uint2*)(xl + (size_t)row * Dsz + d4) = ul;
    }
}

// ================= mean-pool + final dense + sigmoid =================
__global__ __launch_bounds__(256)
void final_kernel(const float* __restrict__ x, const float* __restrict__ Wf,
                  const float* __restrict__ bf_, float* __restrict__ out, int out_size)
{
    const int b = blockIdx.x;
    const float* xb = x + (size_t)b * Ssz * Dsz;
    float acc = 0.f;
    for (int i = threadIdx.x; i < (Ssz * Dsz) / 4; i += 256) {
        float4 v = *(const float4*)(xb + (size_t)i * 4);
        int d = (i * 4) & (Dsz - 1);
        acc += v.x * Wf[d] + v.y * Wf[d+1] + v.z * Wf[d+2] + v.w * Wf[d+3];
    }
    #pragma unroll
    for (int o = 16; o > 0; o >>= 1) acc += __shfl_down_sync(0xffffffffu, acc, o);
    __shared__ float ws[8];
    int warp = threadIdx.x >> 5, lane = threadIdx.x & 31;
    if (lane == 0) ws[warp] = acc;
    __syncthreads();
    if (threadIdx.x == 0) {
        float tot = 0.f;
        #pragma unroll
        for (int w = 0; w < 8; ++w) tot += ws[w];
        float logit = tot * (1.f / (float)Ssz) + bf_[0];
        if (b < out_size) out[b] = logit;
        if (Bsz + b < out_size) out[Bsz + b] = 1.f / (1.f + expf(-logit));
    }
}

// ================= orchestration =================
extern "C" void kernel_launch(void* const* d_in, const int* in_sizes, int n_in,
                              void* d_out, int out_size)
{
    const int*   tok = (const int*)  d_in[0];
    const float* emb = (const float*)d_in[1];
    const float* W0  = (const float*)d_in[2];
    const float* b0  = (const float*)d_in[3];
    const float* Wh  = (const float*)d_in[4];
    const float* bh  = (const float*)d_in[5];
    const float* Wo  = (const float*)d_in[6];
    const float* bo  = (const float*)d_in[7];
    const float* g1  = (const float*)d_in[8];
    const float* be1 = (const float*)d_in[9];
    const float* W1  = (const float*)d_in[10];
    const float* b1  = (const float*)d_in[11];
    const float* W2  = (const float*)d_in[12];
    const float* b2  = (const float*)d_in[13];
    const float* g2  = (const float*)d_in[14];
    const float* be2 = (const float*)d_in[15];
    const float* Wf  = (const float*)d_in[16];
    const float* bf_ = (const float*)d_in[17];
    float* out = (float*)d_out;

    float *x, *y;
    bf16 *qkvh, *qkvl, *xhh, *xhl, *xbh, *xbl, *xch, *xcl, *h1h, *h1l;
    bf16 *woth, *wotl, *w1th, *w1tl, *w2th, *w2tl, *w0th, *w0tl, *whth, *whtl;
    cudaGetSymbolAddress((void**)&x,    g_x);
    cudaGetSymbolAddress((void**)&y,    g_y);
    cudaGetSymbolAddress((void**)&qkvh, g_qkvh);
    cudaGetSymbolAddress((void**)&qkvl, g_qkvl);
    cudaGetSymbolAddress((void**)&xhh,  g_xhh);
    cudaGetSymbolAddress((void**)&xhl,  g_xhl);
    cudaGetSymbolAddress((void**)&xbh,  g_xbh);
    cudaGetSymbolAddress((void**)&xbl,  g_xbl);
    cudaGetSymbolAddress((void**)&xch,  g_xch);
    cudaGetSymbolAddress((void**)&xcl,  g_xcl);
    cudaGetSymbolAddress((void**)&h1h,  g_h1h);
    cudaGetSymbolAddress((void**)&h1l,  g_h1l);
    cudaGetSymbolAddress((void**)&woth, g_woth);
    cudaGetSymbolAddress((void**)&wotl, g_wotl);
    cudaGetSymbolAddress((void**)&w1th, g_w1th);
    cudaGetSymbolAddress((void**)&w1tl, g_w1tl);
    cudaGetSymbolAddress((void**)&w2th, g_w2th);
    cudaGetSymbolAddress((void**)&w2tl, g_w2tl);
    cudaGetSymbolAddress((void**)&w0th, g_w0th);
    cudaGetSymbolAddress((void**)&w0tl, g_w0tl);
    cudaGetSymbolAddress((void**)&whth, g_whth);
    cudaGetSymbolAddress((void**)&whtl, g_whtl);

    cudaFuncSetAttribute(gemm_mma<0>, cudaFuncAttributeMaxDynamicSharedMemorySize, GDYN);
    cudaFuncSetAttribute(gemm_mma<1>, cudaFuncAttributeMaxDynamicSharedMemorySize, GDYN);
    cudaFuncSetAttribute(attn_mma,    cudaFuncAttributeMaxDynamicSharedMemorySize, ATTN_DYN);
    cudaFuncSetAttribute(proj_mma,    cudaFuncAttributeMaxDynamicSharedMemorySize, P_DYN);

    // second stream + fork/join events (created each call, intentionally leaked:
    // not device memory; kernel_launch is invoked only a handful of times)
    cudaStream_t s1;
    cudaStreamCreateWithFlags(&s1, cudaStreamNonBlocking);
    cudaEvent_t eF, eJ;
    cudaEventCreateWithFlags(&eF, cudaEventDisableTiming);
    cudaEventCreateWithFlags(&eJ, cudaEventDisableTiming);

    {
        int64_t tot = (int64_t)Bsz * Ssz * Dsz / 2;
        embed_kernel<<<(unsigned)((tot + 255) / 256), 256>>>(tok, emb, x, xch, xcl);
    }

    wsplit_all<<<WSP_TOTAL, 256>>>(Wo, W1, W2, W0, Wh,
                                   woth, wotl, w1th, w1tl, w2th, w2tl,
                                   w0th, w0tl, whth, whtl);

    const dim3 attn_half(Ssz / 64, Bsz / 2);     // (16, 16) = 256 CTAs per half
    const dim3 tc_wo(Dsz / GBN,  MROWS / GBM);
    const dim3 tc_f1(FFd / GBN,  MROWS / GBM);
    const dim3 tc_f2(Dsz / GBN,  MROWS / GBM);

    // per-half pointer offsets (batches [0,16) on stream0, [16,32) on s1)
    const size_t rowsB  = (size_t)HROWS;             // 16384 rows
    const size_t qkvOff = rowsB * QKVW;
    const size_t actOff = rowsB * Dsz;

    for (int l = 0; l < NBlk; ++l) {
        const bf16* w0h = w0th + (size_t)l * QKVW * Dsz;
        const bf16* w0l = w0tl + (size_t)l * QKVW * Dsz;
        const float* b0l = b0 + (size_t)l * QKVW;

        // fork: s1 waits for LN2/embed output on stream0
        cudaEventRecord(eF, 0);
        cudaStreamWaitEvent(s1, eF, 0);

        // ---- half A (stream 0): head 0 ----
        proj_mma<<<HROWS/128, 128, P_DYN, 0>>>(xch, xcl, Dsz,
            w0h, w0l, b0l, qkvh, qkvl, Dsz);
        attn_mma<<<attn_half, 128, ATTN_DYN, 0>>>(qkvh, qkvl, xhh, xhl);
        // ---- half B (stream s1): head 0 ----
        proj_mma<<<HROWS/128, 128, P_DYN, s1>>>(xch + actOff, xcl + actOff, Dsz,
            w0h, w0l, b0l, qkvh + qkvOff, qkvl + qkvOff, Dsz);
        attn_mma<<<attn_half, 128, ATTN_DYN, s1>>>(qkvh + qkvOff, qkvl + qkvOff,
            xhh + actOff, xhl + actOff);

        // chained heads 1..15
        for (int h = 1; h < Hh; ++h) {
            const size_t wo = ((size_t)l * (Hh - 1) + (h - 1)) * QKVW * DHd;
            const bf16* whh = whth + wo;
            const bf16* whl = whtl + wo;
            const float* bhl = bh + ((size_t)l * (Hh - 1) + (h - 1)) * QKVW;
            const size_t ci = (size_t)(h - 1) * DHd;
            const size_t co = (size_t)h * DHd;

            proj_mma<<<HROWS/128, 128, P_DYN, 0>>>(xhh + ci, xhl + ci, Dsz,
                whh, whl, bhl, qkvh, qkvl, DHd);
            attn_mma<<<attn_half, 128, ATTN_DYN, 0>>>(qkvh, qkvl, xhh + co, xhl + co);

            proj_mma<<<HROWS/128, 128, P_DYN, s1>>>(xhh + actOff + ci, xhl + actOff + ci, Dsz,
                whh, whl, bhl, qkvh + qkvOff, qkvl + qkvOff, DHd);
            attn_mma<<<attn_half, 128, ATTN_DYN, s1>>>(qkvh + qkvOff, qkvl + qkvOff,
                xhh + actOff + co, xhl + actOff + co);
        }

        // join: stream0 waits for half B before the Wo GEMM
        cudaEventRecord(eJ, s1);
        cudaStreamWaitEvent(0, eJ, 0);

        // output projection + residual (mma), then LN1 (emit bf16)
        gemm_mma<0><<<tc_wo, 256, GDYN>>>(xhh, xhl,
            woth + (size_t)l * Dsz * Dsz, wotl + (size_t)l * Dsz * Dsz,
            bo + (size_t)l * Dsz, x, y, nullptr, nullptr, Dsz, Dsz);
        ln_kernel<<<MROWS/4, 128>>>(y, g1 + (size_t)l * Dsz, be1 + (size_t)l * Dsz,
                                    x, xbh, xbl);

        // FFN1 (mma, relu -> bf16 split)
        gemm_mma<1><<<tc_f1, 256, GDYN>>>(xbh, xbl,
            w1th + (size_t)l * FFd * Dsz, w1tl + (size_t)l * FFd * Dsz,
            b1 + (size_t)l * FFd, nullptr, nullptr, h1h, h1l, Dsz, FFd);

        // FFN2 (mma) + residual, then LN2 (emit bf16 for next layer head0)
        gemm_mma<0><<<tc_f2, 256, GDYN>>>(h1h, h1l,
            w2th + (size_t)l * Dsz * FFd, w2tl + (size_t)l * Dsz * FFd,
            b2 + (size_t)l * Dsz, x, y, nullptr, nullptr, FFd, Dsz);
        ln_kernel<<<MROWS/4, 128>>>(y, g2 + (size_t)l * Dsz, be2 + (size_t)l * Dsz,
                                    x, xch, xcl);
    }

    final_kernel<<<Bsz, 256>>>(x, Wf, bf_, out, out_size);
}